// round 2
// baseline (speedup 1.0000x reference)
#include <cuda_runtime.h>
#include <math.h>

#define B_ 64
#define S_ 512
#define H_ 1024
#define I_ 1024
#define N_ (B_*S_)            // 32768 rows
#define SC (0.01f/1024.0f)    // LR / I
#define EPS_ 1e-5f

// ---------------- scratch (device globals; no allocation allowed) ----------------
__device__ float g_T[(long long)N_*I_];        // target = x@Wt + bt
__device__ float g_E[(long long)N_*I_];        // A, then err (in place)
__device__ float g_C[(long long)B_*S_*S_];     // per-batch Gram + 1
__device__ float g_Minv[(long long)B_*8*64*64];// per (batch,chunk) (I+sc*L)^-1
__device__ float g_ttt[(long long)N_*H_];      // silu(inner)@Wo + bo
__device__ float g_Z[(long long)N_*H_];        // gate pre-activation
__device__ float g_DW[H_*I_];                  // W_init - Wt
__device__ float g_Db[I_];                     // b_init - bt

__device__ __forceinline__ float silu_f(float v) { return v / (1.0f + expf(-v)); }

// ---------------- prep: DW = W_init - Wt, Db = b_init - bt ----------------
__global__ void prep_kernel(const float* __restrict__ Wi, const float* __restrict__ Wt,
                            const float* __restrict__ bi, const float* __restrict__ bt) {
    int i = blockIdx.x * 256 + threadIdx.x;
    if (i < H_ * I_) g_DW[i] = Wi[i] - Wt[i];
    if (i < I_)      g_Db[i] = bi[i] - bt[i];
}

// ---------------- generic fp32 GEMM: C[M,N] = opA(A) @ B + bias ----------------
// MODE 0: A = A0 (row-major, lda=K)
// MODE 1: A = silu(A0 + A1) (both row-major, lda=K)
// MODE 2: A = concat(A0, A1) along K (each row length 1024), K = 2048
template<int MODE>
__global__ __launch_bounds__(256) void gemm_kernel(
    const float* __restrict__ A0, const float* __restrict__ A1,
    const float* __restrict__ Bm, const float* __restrict__ bias,
    float* __restrict__ Cm, int M, int N, int K)
{
    __shared__ float As[16][132];
    __shared__ float Bs[16][132];
    const int tid = threadIdx.x;
    const int tx = tid & 15, ty = tid >> 4;
    const int m0 = blockIdx.y << 7, n0 = blockIdx.x << 7;

    float acc[8][8];
#pragma unroll
    for (int i = 0; i < 8; i++)
#pragma unroll
        for (int j = 0; j < 8; j++) acc[i][j] = 0.0f;

    for (int k0 = 0; k0 < K; k0 += 16) {
        // A tile: 128 rows x 16 k, stored transposed As[k][m]
#pragma unroll
        for (int i = 0; i < 2; i++) {
            int slot = tid * 2 + i;          // 0..511
            int row  = slot >> 2;            // 0..127
            int kq   = (slot & 3) << 2;      // 0,4,8,12
            float4 v;
            if (MODE == 2) {
                const float* src = (k0 < 1024) ? A0 : A1;
                int kk = (k0 < 1024) ? (k0 + kq) : (k0 + kq - 1024);
                v = *reinterpret_cast<const float4*>(src + (size_t)(m0 + row) * 1024 + kk);
            } else {
                v = *reinterpret_cast<const float4*>(A0 + (size_t)(m0 + row) * K + k0 + kq);
                if (MODE == 1) {
                    float4 w = *reinterpret_cast<const float4*>(A1 + (size_t)(m0 + row) * K + k0 + kq);
                    v.x = silu_f(v.x + w.x); v.y = silu_f(v.y + w.y);
                    v.z = silu_f(v.z + w.z); v.w = silu_f(v.w + w.w);
                }
            }
            As[kq + 0][row] = v.x; As[kq + 1][row] = v.y;
            As[kq + 2][row] = v.z; As[kq + 3][row] = v.w;
        }
        // B tile: 16 k x 128 n
#pragma unroll
        for (int i = 0; i < 2; i++) {
            int slot = tid * 2 + i;
            int kr = slot >> 5;              // 0..15
            int nq = (slot & 31) << 2;       // 0..124
            float4 v = *reinterpret_cast<const float4*>(Bm + (size_t)(k0 + kr) * N + n0 + nq);
            *reinterpret_cast<float4*>(&Bs[kr][nq]) = v;
        }
        __syncthreads();
#pragma unroll
        for (int k = 0; k < 16; k++) {
            float a[8], b[8];
            *(float4*)&a[0] = *(const float4*)&As[k][ty * 8];
            *(float4*)&a[4] = *(const float4*)&As[k][ty * 8 + 4];
            *(float4*)&b[0] = *(const float4*)&Bs[k][tx * 8];
            *(float4*)&b[4] = *(const float4*)&Bs[k][tx * 8 + 4];
#pragma unroll
            for (int i = 0; i < 8; i++)
#pragma unroll
                for (int j = 0; j < 8; j++) acc[i][j] += a[i] * b[j];
        }
        __syncthreads();
    }
#pragma unroll
    for (int i = 0; i < 8; i++) {
        int row = m0 + ty * 8 + i;
#pragma unroll
        for (int j = 0; j < 8; j += 4) {
            int col = n0 + tx * 8 + j;
            float4 o;
            o.x = acc[i][j + 0] + bias[col + 0];
            o.y = acc[i][j + 1] + bias[col + 1];
            o.z = acc[i][j + 2] + bias[col + 2];
            o.w = acc[i][j + 3] + bias[col + 3];
            *reinterpret_cast<float4*>(Cm + (size_t)row * N + col) = o;
        }
    }
}

// ---------------- per-batch Gram: C[b][t][s] = x_b[t] . x_b[s] + 1 (lower tiles) ----
__global__ __launch_bounds__(256) void gram_kernel(const float* __restrict__ X)
{
    if (blockIdx.x > blockIdx.y) return;   // only lower-triangular tiles needed
    __shared__ float As[16][132];
    __shared__ float Bs[16][132];
    const int tid = threadIdx.x;
    const int tx = tid & 15, ty = tid >> 4;
    const int b = blockIdx.z;
    const int t0 = blockIdx.y << 7, s0 = blockIdx.x << 7;
    const float* xb = X + (size_t)b * S_ * H_;

    float acc[8][8];
#pragma unroll
    for (int i = 0; i < 8; i++)
#pragma unroll
        for (int j = 0; j < 8; j++) acc[i][j] = 0.0f;

    for (int k0 = 0; k0 < H_; k0 += 16) {
#pragma unroll
        for (int i = 0; i < 2; i++) {
            int slot = tid * 2 + i;
            int row = slot >> 2;
            int kq  = (slot & 3) << 2;
            float4 v = *reinterpret_cast<const float4*>(xb + (size_t)(t0 + row) * H_ + k0 + kq);
            As[kq + 0][row] = v.x; As[kq + 1][row] = v.y;
            As[kq + 2][row] = v.z; As[kq + 3][row] = v.w;
            float4 w = *reinterpret_cast<const float4*>(xb + (size_t)(s0 + row) * H_ + k0 + kq);
            Bs[kq + 0][row] = w.x; Bs[kq + 1][row] = w.y;
            Bs[kq + 2][row] = w.z; Bs[kq + 3][row] = w.w;
        }
        __syncthreads();
#pragma unroll
        for (int k = 0; k < 16; k++) {
            float a[8], bb[8];
            *(float4*)&a[0]  = *(const float4*)&As[k][ty * 8];
            *(float4*)&a[4]  = *(const float4*)&As[k][ty * 8 + 4];
            *(float4*)&bb[0] = *(const float4*)&Bs[k][tx * 8];
            *(float4*)&bb[4] = *(const float4*)&Bs[k][tx * 8 + 4];
#pragma unroll
            for (int i = 0; i < 8; i++)
#pragma unroll
                for (int j = 0; j < 8; j++) acc[i][j] += a[i] * bb[j];
        }
        __syncthreads();
    }
    float* Cb = g_C + (size_t)b * S_ * S_;
#pragma unroll
    for (int i = 0; i < 8; i++)
#pragma unroll
        for (int j = 0; j < 8; j++)
            Cb[(size_t)(t0 + ty * 8 + i) * S_ + s0 + tx * 8 + j] = acc[i][j] + 1.0f;
}

// ---------------- triangular inverse: M = (I + sc*L)^-1 per (batch, chunk) --------
__global__ __launch_bounds__(64) void tri_inv_kernel()
{
    __shared__ float L[64][65];
    __shared__ float Msm[64][65];
    const int bc = blockIdx.x;           // b*8 + ch
    const int b = bc >> 3, ch = bc & 7;
    const int j = threadIdx.x;
    const float* Cb = g_C + (size_t)b * S_ * S_ + (size_t)(ch * 64) * S_ + ch * 64;
    for (int r = 0; r < 64; r++) L[r][j] = Cb[(size_t)r * S_ + j];   // coalesced in j
    for (int t = 0; t < 64; t++) Msm[t][j] = (t == j) ? 1.0f : 0.0f;
    __syncthreads();
    // forward substitution, column j private to thread j
    for (int t = 1; t < 64; t++) {
        if (t > j) {
            float a = 0.0f;
            for (int s = j; s < t; s++) a += L[t][s] * Msm[s][j];
            Msm[t][j] = -SC * a;
        }
    }
    float* Mo = g_Minv + (size_t)bc * 64 * 64;
    for (int r = 0; r < 64; r++) Mo[r * 64 + j] = Msm[r][j];
}

// ---------------- chunk solve: E_ch = Minv @ (A_ch - sc * C[ch, <ch] @ E_prev) ----
__global__ __launch_bounds__(128) void solve_chunk_kernel(int ch)
{
    __shared__ float CsT[64][65];    // CsT[p][r] = C[ch*64+r][pc*64+p]  (then Minv^T)
    __shared__ float Ps[64][132];    // E_prev tile / R tile
    const int tid = threadIdx.x;
    const int tx = tid & 15, ty = tid >> 4;   // tx: 16 col-groups of 8, ty: 8 row-groups of 8
    const int b = blockIdx.y;
    const int col0 = blockIdx.x << 7;
    float* Eb = g_E + (size_t)b * S_ * I_;
    const float* Cb = g_C + (size_t)b * S_ * S_;

    float acc[8][8];
#pragma unroll
    for (int r = 0; r < 8; r++)
#pragma unroll
        for (int c = 0; c < 8; c++) acc[r][c] = 0.0f;

    for (int pc = 0; pc < ch; pc++) {
        for (int idx = tid; idx < 64 * 64; idx += 128) {
            int r = idx >> 6, p = idx & 63;
            CsT[p][r] = Cb[(size_t)(ch * 64 + r) * S_ + pc * 64 + p];
        }
        for (int idx = tid; idx < 64 * 128; idx += 128) {
            int p = idx >> 7, jj = idx & 127;
            Ps[p][jj] = Eb[(size_t)(pc * 64 + p) * I_ + col0 + jj];
        }
        __syncthreads();
#pragma unroll 4
        for (int p = 0; p < 64; p++) {
            float a[8], bb[8];
#pragma unroll
            for (int r = 0; r < 8; r++) a[r] = CsT[p][ty * 8 + r];
            *(float4*)&bb[0] = *(const float4*)&Ps[p][tx * 8];
            *(float4*)&bb[4] = *(const float4*)&Ps[p][tx * 8 + 4];
#pragma unroll
            for (int r = 0; r < 8; r++)
#pragma unroll
                for (int c = 0; c < 8; c++) acc[r][c] += a[r] * bb[c];
        }
        __syncthreads();
    }

    // R = A - sc*acc  -> Ps ;  load Minv (transposed) -> CsT
#pragma unroll
    for (int r = 0; r < 8; r++) {
        int row = ty * 8 + r;
        float4 a0 = *(const float4*)(Eb + (size_t)(ch * 64 + row) * I_ + col0 + tx * 8);
        float4 a1 = *(const float4*)(Eb + (size_t)(ch * 64 + row) * I_ + col0 + tx * 8 + 4);
        Ps[row][tx * 8 + 0] = a0.x - SC * acc[r][0];
        Ps[row][tx * 8 + 1] = a0.y - SC * acc[r][1];
        Ps[row][tx * 8 + 2] = a0.z - SC * acc[r][2];
        Ps[row][tx * 8 + 3] = a0.w - SC * acc[r][3];
        Ps[row][tx * 8 + 4] = a1.x - SC * acc[r][4];
        Ps[row][tx * 8 + 5] = a1.y - SC * acc[r][5];
        Ps[row][tx * 8 + 6] = a1.z - SC * acc[r][6];
        Ps[row][tx * 8 + 7] = a1.w - SC * acc[r][7];
    }
    const float* Mo = g_Minv + (size_t)(b * 8 + ch) * 64 * 64;
    for (int idx = tid; idx < 64 * 64; idx += 128) {
        int row = idx >> 6, q = idx & 63;
        CsT[q][row] = Mo[idx];          // CsT[q][row] = M[row][q]
    }
    __syncthreads();

    float outr[8][8];
#pragma unroll
    for (int r = 0; r < 8; r++)
#pragma unroll
        for (int c = 0; c < 8; c++) outr[r][c] = 0.0f;
#pragma unroll 4
    for (int q = 0; q < 64; q++) {
        float a[8], bb[8];
#pragma unroll
        for (int r = 0; r < 8; r++) a[r] = CsT[q][ty * 8 + r];
        *(float4*)&bb[0] = *(const float4*)&Ps[q][tx * 8];
        *(float4*)&bb[4] = *(const float4*)&Ps[q][tx * 8 + 4];
#pragma unroll
        for (int r = 0; r < 8; r++)
#pragma unroll
            for (int c = 0; c < 8; c++) outr[r][c] += a[r] * bb[c];
    }
#pragma unroll
    for (int r = 0; r < 8; r++) {
        int row = ty * 8 + r;
        float4 o0 = make_float4(outr[r][0], outr[r][1], outr[r][2], outr[r][3]);
        float4 o1 = make_float4(outr[r][4], outr[r][5], outr[r][6], outr[r][7]);
        *(float4*)(Eb + (size_t)(ch * 64 + row) * I_ + col0 + tx * 8)     = o0;
        *(float4*)(Eb + (size_t)(ch * 64 + row) * I_ + col0 + tx * 8 + 4) = o1;
    }
}

// ---------------- fused sigmoid-gate + LayerNorm epilogue ----------------
__global__ __launch_bounds__(256) void gate_ln_kernel(
    const float* __restrict__ Z, const float* __restrict__ T, const float* __restrict__ X,
    const float* __restrict__ gamma, const float* __restrict__ beta, float* __restrict__ out)
{
    __shared__ float red[16];
    __shared__ float mu_s, rinv_s;
    const int n = blockIdx.x, tid = threadIdx.x;
    const size_t base = (size_t)n * H_ + tid * 4;
    float4 z = *(const float4*)(Z + base);
    float4 t = *(const float4*)(T + base);
    float4 x = *(const float4*)(X + base);
    float h[4];
    {
        float g;
        g = 1.0f / (1.0f + expf(-z.x)); h[0] = g * t.x + (1.0f - g) * x.x;
        g = 1.0f / (1.0f + expf(-z.y)); h[1] = g * t.y + (1.0f - g) * x.y;
        g = 1.0f / (1.0f + expf(-z.z)); h[2] = g * t.z + (1.0f - g) * x.z;
        g = 1.0f / (1.0f + expf(-z.w)); h[3] = g * t.w + (1.0f - g) * x.w;
    }
    float s = h[0] + h[1] + h[2] + h[3];
    float q = h[0]*h[0] + h[1]*h[1] + h[2]*h[2] + h[3]*h[3];
#pragma unroll
    for (int o = 16; o > 0; o >>= 1) {
        s += __shfl_xor_sync(0xffffffffu, s, o);
        q += __shfl_xor_sync(0xffffffffu, q, o);
    }
    const int lane = tid & 31, wid = tid >> 5;
    if (lane == 0) { red[wid] = s; red[8 + wid] = q; }
    __syncthreads();
    if (tid == 0) {
        float S = 0.0f, Q = 0.0f;
#pragma unroll
        for (int w = 0; w < 8; w++) { S += red[w]; Q += red[8 + w]; }
        float mu = S * (1.0f / H_);
        float var = Q * (1.0f / H_) - mu * mu;
        mu_s = mu; rinv_s = rsqrtf(var + EPS_);
    }
    __syncthreads();
    const float mu = mu_s, rinv = rinv_s;
    float4 gm = *(const float4*)(gamma + tid * 4);
    float4 bt = *(const float4*)(beta + tid * 4);
    float4 o;
    o.x = (h[0] - mu) * rinv * gm.x + bt.x;
    o.y = (h[1] - mu) * rinv * gm.y + bt.y;
    o.z = (h[2] - mu) * rinv * gm.z + bt.z;
    o.w = (h[3] - mu) * rinv * gm.w + bt.w;
    *(float4*)(out + base) = o;
}

// ---------------- launch ----------------
extern "C" void kernel_launch(void* const* d_in, const int* in_sizes, int n_in,
                              void* d_out, int out_size)
{
    const float* x      = (const float*)d_in[0];
    const float* W_init = (const float*)d_in[1];
    const float* b_init = (const float*)d_in[2];
    const float* Wt     = (const float*)d_in[3];
    const float* bt     = (const float*)d_in[4];
    const float* Wo     = (const float*)d_in[5];
    const float* bo     = (const float*)d_in[6];
    const float* Wg     = (const float*)d_in[7];
    const float* bg     = (const float*)d_in[8];
    const float* gamma  = (const float*)d_in[9];
    const float* beta   = (const float*)d_in[10];
    float* out = (float*)d_out;

    float *pT, *pE, *pTT, *pZ, *pDW, *pDb;
    cudaGetSymbolAddress((void**)&pT,  g_T);
    cudaGetSymbolAddress((void**)&pE,  g_E);
    cudaGetSymbolAddress((void**)&pTT, g_ttt);
    cudaGetSymbolAddress((void**)&pZ,  g_Z);
    cudaGetSymbolAddress((void**)&pDW, g_DW);
    cudaGetSymbolAddress((void**)&pDb, g_Db);

    // 1) DW = W_init - Wt, Db = b_init - bt
    prep_kernel<<<4096, 256>>>(W_init, Wt, b_init, bt);
    // 2) T = x @ Wt + bt
    gemm_kernel<0><<<dim3(8, 256), 256>>>(x, nullptr, Wt, bt, pT, N_, I_, H_);
    // 3) A = x @ DW + Db   (into g_E, solved in place)
    gemm_kernel<0><<<dim3(8, 256), 256>>>(x, nullptr, pDW, pDb, pE, N_, I_, H_);
    // 4) Gram (lower tiles): C_b = x_b x_b^T + 1
    gram_kernel<<<dim3(4, 4, 64), 256>>>(x);
    // 5) all chunk-diagonal inverses (depend only on C — fully parallel upfront)
    tri_inv_kernel<<<512, 64>>>();
    // 6) 8 sequential chunk solves (pure mini-GEMMs)
    for (int ch = 0; ch < 8; ch++)
        solve_chunk_kernel<<<dim3(8, 64), 128>>>(ch);
    // 7) ttt = silu(E + T) @ Wo + bo
    gemm_kernel<1><<<dim3(8, 256), 256>>>(pE, pT, Wo, bo, pTT, N_, H_, I_);
    // 8) Z = concat(x, ttt) @ Wg + bg
    gemm_kernel<2><<<dim3(8, 256), 256>>>(x, pTT, Wg, bg, pZ, N_, H_, 2 * H_);
    // 9) out = LayerNorm(sigmoid(Z)*ttt + (1-sigmoid(Z))*x)
    gate_ln_kernel<<<N_, 256>>>(pZ, pTT, x, gamma, beta, out);
}

// round 7
// speedup vs baseline: 2.2912x; 2.2912x over previous
#include <cuda_runtime.h>
#include <cuda_fp16.h>
#include <cstdint>
#include <math.h>

#define B_ 64
#define S_ 512
#define H_ 1024
#define I_ 1024
#define N_ (B_*S_)
#define SC (0.01f/1024.0f)
#define EPS_ 1e-5f

// ================= scratch =================
__device__ float  g_TE[(size_t)N_*2048];      // [T | A->E], ld=2048 (fp32)
__device__ float  g_ttt[(size_t)N_*H_];
__device__ float  g_Z[(size_t)N_*H_];
__device__ float  g_C[(size_t)B_*S_*S_];
__device__ float  g_Minv[(size_t)B_*8*64*64];
__device__ float  g_bcat[2048];
__device__ __half g_xh[(size_t)N_*H_];
__device__ __half g_xl[(size_t)N_*H_];
__device__ __half g_Sh[(size_t)N_*I_];
__device__ __half g_Sl[(size_t)N_*I_];
__device__ __half g_TTh[(size_t)N_*H_];
__device__ __half g_TTl[(size_t)N_*H_];
__device__ __half g_Bh[(size_t)2048*1024];    // [Wt | Winit-Wt]^T  [n=2048][k=1024]
__device__ __half g_Bl[(size_t)2048*1024];
__device__ __half g_Woh[(size_t)1024*1024];   // Wo^T
__device__ __half g_Wol[(size_t)1024*1024];
__device__ __half g_Wgh[(size_t)1024*2048];   // Wg^T [n=1024][k=2048]
__device__ __half g_Wgl[(size_t)1024*2048];

__constant__ int c_TI[10] = {0,1,1,2,2,2,3,3,3,3};
__constant__ int c_TJ[10] = {0,0,1,0,1,2,0,1,2,3};

// ================= helpers =================
__device__ __forceinline__ uint32_t smem_u32(const void* p) {
    uint32_t a;
    asm("{ .reg .u64 t; cvta.to.shared.u64 t, %1; cvt.u32.u64 %0, t; }" : "=r"(a) : "l"(p));
    return a;
}
__device__ __forceinline__ void hsplit(float v, __half& h, __half& l) {
    h = __float2half_rn(v);
    l = __float2half_rn(v - __half2float(h));
}
__device__ __forceinline__ float silu_f(float v) { return v / (1.0f + expf(-v)); }

__device__ __forceinline__ void ldm_x4(uint32_t* r, uint32_t addr) {
    asm volatile("ldmatrix.sync.aligned.m8n8.x4.shared.b16 {%0,%1,%2,%3}, [%4];"
        : "=r"(r[0]), "=r"(r[1]), "=r"(r[2]), "=r"(r[3]) : "r"(addr));
}
__device__ __forceinline__ void mma16816(float* d, const uint32_t* a, uint32_t b0, uint32_t b1) {
    asm volatile("mma.sync.aligned.m16n8k16.row.col.f32.f16.f16.f32 "
        "{%0,%1,%2,%3},{%4,%5,%6,%7},{%8,%9},{%0,%1,%2,%3};"
        : "+f"(d[0]), "+f"(d[1]), "+f"(d[2]), "+f"(d[3])
        : "r"(a[0]), "r"(a[1]), "r"(a[2]), "r"(a[3]), "r"(b0), "r"(b1));
}

// cp.async a 128-row x 32-half tile (64B/row) with XOR-swizzled 16B chunks
__device__ __forceinline__ void cp_tile(__half* s, const __half* __restrict__ g,
                                        size_t row0, int ld, int k, int tid) {
#pragma unroll
    for (int i = 0; i < 2; i++) {
        int cid = tid + 256 * i;            // 0..511
        int row = cid >> 2, c = cid & 3;    // 4 x 16B chunks per row
        const __half* gp = g + (row0 + (size_t)row) * (size_t)ld + k + c * 8;
        int sc = c ^ ((row >> 1) & 3);
        uint32_t d = smem_u32(s + row * 32 + sc * 8);
        asm volatile("cp.async.cg.shared.global [%0], [%1], 16;" :: "r"(d), "l"(gp));
    }
}

// ============ mma.sync fp16-3x GEMM ============
// MODE 0: C[M,N] = A@B^T + bias   (A h/l [M,1024]; B h/l [N,K=1024])
// MODE 1: A = concat(A0,A1) along K (K=2048), B [N,2048]
// MODE 2: gram (1-pass fp16-hi): per-batch lower tiles of x_b x_b^T + 1
// EPI 1: also write hi/lo fp16 split of C
template<int MODE, int EPI>
__global__ __launch_bounds__(256)
void gemm_mma(const __half* __restrict__ Ah0, const __half* __restrict__ Al0,
              const __half* __restrict__ Ah1, const __half* __restrict__ Al1,
              const __half* __restrict__ Bh, const __half* __restrict__ Bl,
              const float* __restrict__ bias,
              float* __restrict__ C, __half* __restrict__ Ch, __half* __restrict__ Cl,
              int ldb, int ldc)
{
    extern __shared__ __align__(16) __half smem[];
    __half* sA = smem;               // 3 x 4096 halves
    __half* sB = smem + 3 * 4096;    // 3 x 4096 halves

    const int tid = threadIdx.x;
    const int warp = tid >> 5, lane = tid & 31;
    const int warpM = warp & 3, warpN = warp >> 2;   // 4 x 2 warps
    const int KPH = (MODE == 1) ? 2048 : 1024;
    const int NS = ((MODE == 2) ? 1 : 3) * (KPH >> 5);

    size_t arow, brow; int crow0, ccol0, ldcc; float* cb;
    if (MODE == 2) {
        const int b = blockIdx.y;
        crow0 = c_TI[blockIdx.x] << 7; ccol0 = c_TJ[blockIdx.x] << 7;
        arow = (size_t)b * S_ + crow0; brow = (size_t)b * S_ + ccol0;
        cb = C + (size_t)b * S_ * S_; ldcc = S_;
    } else {
        arow = (size_t)blockIdx.y << 7; brow = (size_t)blockIdx.x << 7;
        crow0 = (int)arow; ccol0 = (int)brow; cb = C; ldcc = ldc;
    }

#define LOAD_STAGE(s_) do { \
        const int s__ = (s_); \
        const int k0_ = (s__ % (KPH >> 5)) << 5; \
        const int ph_ = s__ / (KPH >> 5); \
        const __half *ga_, *gb_; int ak_; \
        if (MODE == 2) { ga_ = Ah0; gb_ = Ah0; ak_ = k0_; } \
        else { \
            if (MODE == 1 && k0_ >= 1024) { ga_ = (ph_ == 1) ? Al1 : Ah1; ak_ = k0_ - 1024; } \
            else                          { ga_ = (ph_ == 1) ? Al0 : Ah0; ak_ = k0_; } \
            gb_ = (ph_ == 2) ? Bl : Bh; \
        } \
        cp_tile(sA + (s__ % 3) * 4096, ga_, arow, 1024, ak_, tid); \
        cp_tile(sB + (s__ % 3) * 4096, gb_, brow, (MODE == 2) ? 1024 : ldb, \
                (MODE == 2) ? ak_ : k0_, tid); \
        asm volatile("cp.async.commit_group;" ::: "memory"); \
    } while (0)

    float acc[2][8][4];
#pragma unroll
    for (int mt = 0; mt < 2; mt++)
#pragma unroll
        for (int j = 0; j < 8; j++)
#pragma unroll
            for (int q = 0; q < 4; q++) acc[mt][j][q] = 0.0f;

    LOAD_STAGE(0);
    if (NS > 1) LOAD_STAGE(1);
    asm volatile("cp.async.wait_group 1;" ::: "memory");
    __syncthreads();

    for (int s = 0; s < NS; s++) {
        if (s + 2 < NS) LOAD_STAGE(s + 2);
        const __half* A = sA + (s % 3) * 4096;
        const __half* B = sB + (s % 3) * 4096;
#pragma unroll
        for (int kk = 0; kk < 2; kk++) {
            uint32_t af[2][4];
#pragma unroll
            for (int mt = 0; mt < 2; mt++) {
                const int q = lane >> 3, r = lane & 7;
                const int row = warpM * 32 + mt * 16 + ((q & 1) ? 8 : 0) + r;
                const int c = kk * 2 + (q >> 1);
                ldm_x4(af[mt], smem_u32(A + row * 32 + (c ^ ((row >> 1) & 3)) * 8));
            }
            uint32_t bf[4][4];
#pragma unroll
            for (int nt = 0; nt < 4; nt++) {
                const int q = lane >> 3, r = lane & 7;
                const int row = warpN * 64 + nt * 16 + ((q >> 1) ? 8 : 0) + r;
                const int c = kk * 2 + (q & 1);
                ldm_x4(bf[nt], smem_u32(B + row * 32 + (c ^ ((row >> 1) & 3)) * 8));
            }
#pragma unroll
            for (int mt = 0; mt < 2; mt++)
#pragma unroll
                for (int nt = 0; nt < 4; nt++) {
                    mma16816(acc[mt][nt * 2 + 0], af[mt], bf[nt][0], bf[nt][1]);
                    mma16816(acc[mt][nt * 2 + 1], af[mt], bf[nt][2], bf[nt][3]);
                }
        }
        if (s + 1 < NS) {
            if (s + 2 < NS) asm volatile("cp.async.wait_group 1;" ::: "memory");
            else            asm volatile("cp.async.wait_group 0;" ::: "memory");
            __syncthreads();
        }
    }
#undef LOAD_STAGE

    // epilogue
    const int baseRow = crow0 + warpM * 32;
    const int baseCol = ccol0 + warpN * 64;
#pragma unroll
    for (int mt = 0; mt < 2; mt++) {
#pragma unroll
        for (int j = 0; j < 8; j++) {
            const int col = baseCol + j * 8 + (lane & 3) * 2;
            const int r0 = baseRow + mt * 16 + (lane >> 2);
            float bx, by;
            if (MODE == 2) { bx = 1.0f; by = 1.0f; }
            else { bx = bias[col]; by = bias[col + 1]; }
            float v0 = acc[mt][j][0] + bx, v1 = acc[mt][j][1] + by;
            float v2 = acc[mt][j][2] + bx, v3 = acc[mt][j][3] + by;
            *reinterpret_cast<float2*>(cb + (size_t)r0 * ldcc + col) = make_float2(v0, v1);
            *reinterpret_cast<float2*>(cb + (size_t)(r0 + 8) * ldcc + col) = make_float2(v2, v3);
            if (EPI == 1) {
                __half h0, l0, h1, l1, h2, l2, h3, l3;
                hsplit(v0, h0, l0); hsplit(v1, h1, l1);
                hsplit(v2, h2, l2); hsplit(v3, h3, l3);
                *reinterpret_cast<__half2*>(Ch + (size_t)r0 * ldcc + col) = __halves2half2(h0, h1);
                *reinterpret_cast<__half2*>(Cl + (size_t)r0 * ldcc + col) = __halves2half2(l0, l1);
                *reinterpret_cast<__half2*>(Ch + (size_t)(r0 + 8) * ldcc + col) = __halves2half2(h2, h3);
                *reinterpret_cast<__half2*>(Cl + (size_t)(r0 + 8) * ldcc + col) = __halves2half2(l2, l3);
            }
        }
    }
}

// ================= prep kernels =================
__global__ void split_x_kernel(const float* __restrict__ x, __half* __restrict__ xh,
                               __half* __restrict__ xl) {
    size_t i = ((size_t)blockIdx.x * 256 + threadIdx.x) * 4;
    float4 v = *reinterpret_cast<const float4*>(x + i);
    __half h0, l0, h1, l1, h2, l2, h3, l3;
    hsplit(v.x, h0, l0); hsplit(v.y, h1, l1); hsplit(v.z, h2, l2); hsplit(v.w, h3, l3);
    *reinterpret_cast<__half2*>(xh + i)     = __halves2half2(h0, h1);
    *reinterpret_cast<__half2*>(xh + i + 2) = __halves2half2(h2, h3);
    *reinterpret_cast<__half2*>(xl + i)     = __halves2half2(l0, l1);
    *reinterpret_cast<__half2*>(xl + i + 2) = __halves2half2(l2, l3);
}

// out[(n+roff)*ldo + k] = split(W[k][n] - Wsub?[k][n]);  W is [K, N] row-major
__global__ void tsplit_kernel(const float* __restrict__ W, const float* __restrict__ Wsub,
                              __half* __restrict__ oh, __half* __restrict__ ol,
                              int N, int ldo, int roff)
{
    __shared__ float t[32][33];
    const int k0 = blockIdx.x * 32, n0 = blockIdx.y * 32;
    const int tx = threadIdx.x, ty = threadIdx.y;
#pragma unroll
    for (int i = 0; i < 32; i += 8) {
        float v = W[(size_t)(k0 + ty + i) * N + n0 + tx];
        if (Wsub) v -= Wsub[(size_t)(k0 + ty + i) * N + n0 + tx];
        t[ty + i][tx] = v;
    }
    __syncthreads();
#pragma unroll
    for (int i = 0; i < 32; i += 8) {
        __half h, l;
        hsplit(t[tx][ty + i], h, l);
        oh[(size_t)(n0 + ty + i + roff) * ldo + k0 + tx] = h;
        ol[(size_t)(n0 + ty + i + roff) * ldo + k0 + tx] = l;
    }
}

__global__ void bcat_kernel(const float* __restrict__ bt, const float* __restrict__ bi,
                            float* __restrict__ bc) {
    int j = blockIdx.x * 256 + threadIdx.x;
    if (j < 1024) bc[j] = bt[j];
    else if (j < 2048) bc[j] = bi[j - 1024] - bt[j - 1024];
}

// S = silu(T + E) from g_TE (ld 2048) -> fp16 hi/lo (ld 1024)
__global__ void silu_split_kernel(__half* __restrict__ Sh, __half* __restrict__ Sl) {
    size_t idx4 = (size_t)blockIdx.x * 256 + threadIdx.x;
    size_t r = idx4 >> 8, j4 = (idx4 & 255) * 4;
    size_t base = r * 2048 + j4;
    float4 t = *reinterpret_cast<const float4*>(g_TE + base);
    float4 e = *reinterpret_cast<const float4*>(g_TE + base + 1024);
    float s0 = silu_f(t.x + e.x), s1 = silu_f(t.y + e.y);
    float s2 = silu_f(t.z + e.z), s3 = silu_f(t.w + e.w);
    __half h0, l0, h1, l1, h2, l2, h3, l3;
    hsplit(s0, h0, l0); hsplit(s1, h1, l1); hsplit(s2, h2, l2); hsplit(s3, h3, l3);
    size_t ob = r * 1024 + j4;
    *reinterpret_cast<__half2*>(Sh + ob)     = __halves2half2(h0, h1);
    *reinterpret_cast<__half2*>(Sh + ob + 2) = __halves2half2(h2, h3);
    *reinterpret_cast<__half2*>(Sl + ob)     = __halves2half2(l0, l1);
    *reinterpret_cast<__half2*>(Sl + ob + 2) = __halves2half2(l2, l3);
}

// ================= triangular inverse per (batch, chunk) =================
__global__ __launch_bounds__(64) void tri_inv_kernel()
{
    __shared__ float L[64][65];
    __shared__ float Msm[64][65];
    const int bc = blockIdx.x, b = bc >> 3, ch = bc & 7;
    const int j = threadIdx.x;
    const float* Cb = g_C + (size_t)b * S_ * S_ + (size_t)(ch * 64) * S_ + ch * 64;
    for (int r = 0; r < 64; r++) L[r][j] = Cb[(size_t)r * S_ + j];
    for (int t = 0; t < 64; t++) Msm[t][j] = (t == j) ? 1.0f : 0.0f;
    __syncthreads();
    for (int t = 1; t < 64; t++) {
        if (t > j) {
            float a = 0.0f;
            for (int s = j; s < t; s++) a += L[t][s] * Msm[s][j];
            Msm[t][j] = -SC * a;
        }
    }
    float* Mo = g_Minv + (size_t)bc * 64 * 64;
    for (int r = 0; r < 64; r++) Mo[r * 64 + j] = Msm[r][j];
}

// ================= chunk solve (E in g_TE cols [1024,2048), ld 2048) =================
__global__ __launch_bounds__(128) void solve_chunk_kernel(int ch)
{
    __shared__ float CsT[64][65];
    __shared__ float Ps[64][132];
    const int tid = threadIdx.x;
    const int tx = tid & 15, ty = tid >> 4;
    const int b = blockIdx.y;
    const int col0 = blockIdx.x << 7;
    float* Eb = g_TE + (size_t)b * S_ * 2048 + 1024;
    const float* Cb = g_C + (size_t)b * S_ * S_;

    float acc[8][8];
#pragma unroll
    for (int r = 0; r < 8; r++)
#pragma unroll
        for (int c = 0; c < 8; c++) acc[r][c] = 0.0f;

    for (int pc = 0; pc < ch; pc++) {
        for (int idx = tid; idx < 64 * 64; idx += 128) {
            int r = idx >> 6, p = idx & 63;
            CsT[p][r] = Cb[(size_t)(ch * 64 + r) * S_ + pc * 64 + p];
        }
        for (int idx = tid; idx < 64 * 128; idx += 128) {
            int p = idx >> 7, jj = idx & 127;
            Ps[p][jj] = Eb[(size_t)(pc * 64 + p) * 2048 + col0 + jj];
        }
        __syncthreads();
#pragma unroll 4
        for (int p = 0; p < 64; p++) {
            float a[8], bb[8];
#pragma unroll
            for (int r = 0; r < 8; r++) a[r] = CsT[p][ty * 8 + r];
            *(float4*)&bb[0] = *(const float4*)&Ps[p][tx * 8];
            *(float4*)&bb[4] = *(const float4*)&Ps[p][tx * 8 + 4];
#pragma unroll
            for (int r = 0; r < 8; r++)
#pragma unroll
                for (int c = 0; c < 8; c++) acc[r][c] += a[r] * bb[c];
        }
        __syncthreads();
    }

#pragma unroll
    for (int r = 0; r < 8; r++) {
        int row = ty * 8 + r;
        float4 a0 = *(const float4*)(Eb + (size_t)(ch * 64 + row) * 2048 + col0 + tx * 8);
        float4 a1 = *(const float4*)(Eb + (size_t)(ch * 64 + row) * 2048 + col0 + tx * 8 + 4);
        Ps[row][tx * 8 + 0] = a0.x - SC * acc[r][0];
        Ps[row][tx * 8 + 1] = a0.y - SC * acc[r][1];
        Ps[row][tx * 8 + 2] = a0.z - SC * acc[r][2];
        Ps[row][tx * 8 + 3] = a0.w - SC * acc[r][3];
        Ps[row][tx * 8 + 4] = a1.x - SC * acc[r][4];
        Ps[row][tx * 8 + 5] = a1.y - SC * acc[r][5];
        Ps[row][tx * 8 + 6] = a1.z - SC * acc[r][6];
        Ps[row][tx * 8 + 7] = a1.w - SC * acc[r][7];
    }
    const float* Mo = g_Minv + (size_t)(b * 8 + ch) * 64 * 64;
    for (int idx = tid; idx < 64 * 64; idx += 128) {
        int row = idx >> 6, q = idx & 63;
        CsT[q][row] = Mo[idx];
    }
    __syncthreads();

    float outr[8][8];
#pragma unroll
    for (int r = 0; r < 8; r++)
#pragma unroll
        for (int c = 0; c < 8; c++) outr[r][c] = 0.0f;
#pragma unroll 4
    for (int q = 0; q < 64; q++) {
        float a[8], bb[8];
#pragma unroll
        for (int r = 0; r < 8; r++) a[r] = CsT[q][ty * 8 + r];
        *(float4*)&bb[0] = *(const float4*)&Ps[q][tx * 8];
        *(float4*)&bb[4] = *(const float4*)&Ps[q][tx * 8 + 4];
#pragma unroll
        for (int r = 0; r < 8; r++)
#pragma unroll
            for (int c = 0; c < 8; c++) outr[r][c] += a[r] * bb[c];
    }
#pragma unroll
    for (int r = 0; r < 8; r++) {
        int row = ty * 8 + r;
        *(float4*)(Eb + (size_t)(ch * 64 + row) * 2048 + col0 + tx * 8) =
            make_float4(outr[r][0], outr[r][1], outr[r][2], outr[r][3]);
        *(float4*)(Eb + (size_t)(ch * 64 + row) * 2048 + col0 + tx * 8 + 4) =
            make_float4(outr[r][4], outr[r][5], outr[r][6], outr[r][7]);
    }
}

// ================= fused sigmoid-gate + LayerNorm =================
__global__ __launch_bounds__(256) void gate_ln_kernel(
    const float* __restrict__ Z, const float* __restrict__ T, const float* __restrict__ X,
    const float* __restrict__ gamma, const float* __restrict__ beta, float* __restrict__ out)
{
    __shared__ float red[16];
    __shared__ float mu_s, rinv_s;
    const int n = blockIdx.x, tid = threadIdx.x;
    const size_t base = (size_t)n * H_ + tid * 4;
    float4 z = *(const float4*)(Z + base);
    float4 t = *(const float4*)(T + base);
    float4 x = *(const float4*)(X + base);
    float h[4];
    {
        float g;
        g = 1.0f / (1.0f + expf(-z.x)); h[0] = g * t.x + (1.0f - g) * x.x;
        g = 1.0f / (1.0f + expf(-z.y)); h[1] = g * t.y + (1.0f - g) * x.y;
        g = 1.0f / (1.0f + expf(-z.z)); h[2] = g * t.z + (1.0f - g) * x.z;
        g = 1.0f / (1.0f + expf(-z.w)); h[3] = g * t.w + (1.0f - g) * x.w;
    }
    float s = h[0] + h[1] + h[2] + h[3];
    float q = h[0]*h[0] + h[1]*h[1] + h[2]*h[2] + h[3]*h[3];
#pragma unroll
    for (int o = 16; o > 0; o >>= 1) {
        s += __shfl_xor_sync(0xffffffffu, s, o);
        q += __shfl_xor_sync(0xffffffffu, q, o);
    }
    const int lane = tid & 31, wid = tid >> 5;
    if (lane == 0) { red[wid] = s; red[8 + wid] = q; }
    __syncthreads();
    if (tid == 0) {
        float Sa = 0.0f, Q = 0.0f;
#pragma unroll
        for (int w = 0; w < 8; w++) { Sa += red[w]; Q += red[8 + w]; }
        float mu = Sa * (1.0f / H_);
        mu_s = mu; rinv_s = rsqrtf(Q * (1.0f / H_) - mu * mu + EPS_);
    }
    __syncthreads();
    const float mu = mu_s, rinv = rinv_s;
    float4 gm = *(const float4*)(gamma + tid * 4);
    float4 bt = *(const float4*)(beta + tid * 4);
    float4 o;
    o.x = (h[0] - mu) * rinv * gm.x + bt.x;
    o.y = (h[1] - mu) * rinv * gm.y + bt.y;
    o.z = (h[2] - mu) * rinv * gm.z + bt.z;
    o.w = (h[3] - mu) * rinv * gm.w + bt.w;
    *(float4*)(out + base) = o;
}

// ================= launch =================
extern "C" void kernel_launch(void* const* d_in, const int* in_sizes, int n_in,
                              void* d_out, int out_size)
{
    const float* x      = (const float*)d_in[0];
    const float* W_init = (const float*)d_in[1];
    const float* b_init = (const float*)d_in[2];
    const float* Wt     = (const float*)d_in[3];
    const float* bt     = (const float*)d_in[4];
    const float* Wo     = (const float*)d_in[5];
    const float* bo     = (const float*)d_in[6];
    const float* Wg     = (const float*)d_in[7];
    const float* bg     = (const float*)d_in[8];
    const float* gamma  = (const float*)d_in[9];
    const float* beta   = (const float*)d_in[10];
    float* out = (float*)d_out;

    float *pTE, *pTT, *pZ, *pC, *pbc;
    __half *pxh, *pxl, *pSh, *pSl, *pTTh, *pTTl, *pBh, *pBl, *pWoh, *pWol, *pWgh, *pWgl;
    cudaGetSymbolAddress((void**)&pTE,  g_TE);
    cudaGetSymbolAddress((void**)&pTT,  g_ttt);
    cudaGetSymbolAddress((void**)&pZ,   g_Z);
    cudaGetSymbolAddress((void**)&pC,   g_C);
    cudaGetSymbolAddress((void**)&pbc,  g_bcat);
    cudaGetSymbolAddress((void**)&pxh,  g_xh);
    cudaGetSymbolAddress((void**)&pxl,  g_xl);
    cudaGetSymbolAddress((void**)&pSh,  g_Sh);
    cudaGetSymbolAddress((void**)&pSl,  g_Sl);
    cudaGetSymbolAddress((void**)&pTTh, g_TTh);
    cudaGetSymbolAddress((void**)&pTTl, g_TTl);
    cudaGetSymbolAddress((void**)&pBh,  g_Bh);
    cudaGetSymbolAddress((void**)&pBl,  g_Bl);
    cudaGetSymbolAddress((void**)&pWoh, g_Woh);
    cudaGetSymbolAddress((void**)&pWol, g_Wol);
    cudaGetSymbolAddress((void**)&pWgh, g_Wgh);
    cudaGetSymbolAddress((void**)&pWgl, g_Wgl);

    const int SMB = 3 * 4096 * 2 * 2;   // 49152 bytes (3 stages x (A+B) x 8KB)
    cudaFuncSetAttribute(gemm_mma<0,0>, cudaFuncAttributeMaxDynamicSharedMemorySize, SMB);
    cudaFuncSetAttribute(gemm_mma<0,1>, cudaFuncAttributeMaxDynamicSharedMemorySize, SMB);
    cudaFuncSetAttribute(gemm_mma<1,0>, cudaFuncAttributeMaxDynamicSharedMemorySize, SMB);
    cudaFuncSetAttribute(gemm_mma<2,0>, cudaFuncAttributeMaxDynamicSharedMemorySize, SMB);

    dim3 tb(32, 8);
    split_x_kernel<<<N_ * H_ / 1024, 256>>>(x, pxh, pxl);
    tsplit_kernel<<<dim3(32, 32), tb>>>(Wt, nullptr, pBh, pBl, 1024, 1024, 0);
    tsplit_kernel<<<dim3(32, 32), tb>>>(W_init, Wt, pBh, pBl, 1024, 1024, 1024);
    tsplit_kernel<<<dim3(32, 32), tb>>>(Wo, nullptr, pWoh, pWol, 1024, 1024, 0);
    tsplit_kernel<<<dim3(64, 32), tb>>>(Wg, nullptr, pWgh, pWgl, 1024, 2048, 0);
    bcat_kernel<<<8, 256>>>(bt, b_init, pbc);

    // [T | A] = x @ [Wt | Winit-Wt] + [bt | binit-bt]  (N=2048)
    gemm_mma<0,0><<<dim3(16, 256), 256, SMB>>>(pxh, pxl, nullptr, nullptr,
                                               pBh, pBl, pbc, pTE, nullptr, nullptr, 1024, 2048);
    // Gram lower tiles: C_b = x_b x_b^T + 1 (1-pass fp16-hi)
    gemm_mma<2,0><<<dim3(10, 64), 256, SMB>>>(pxh, nullptr, nullptr, nullptr,
                                              nullptr, nullptr, nullptr, pC, nullptr, nullptr,
                                              1024, 0);
    tri_inv_kernel<<<512, 64>>>();
    for (int ch = 0; ch < 8; ch++)
        solve_chunk_kernel<<<dim3(8, 64), 128>>>(ch);
    // S = silu(T + E), fp16 split
    silu_split_kernel<<<N_ * H_ / 1024, 256>>>(pSh, pSl);
    // ttt = S @ Wo + bo (EPI also writes fp16 split)
    gemm_mma<0,1><<<dim3(8, 256), 256, SMB>>>(pSh, pSl, nullptr, nullptr,
                                              pWoh, pWol, bo, pTT, pTTh, pTTl, 1024, 1024);
    // Z = [x, ttt] @ Wg + bg
    gemm_mma<1,0><<<dim3(8, 256), 256, SMB>>>(pxh, pxl, pTTh, pTTl,
                                              pWgh, pWgl, bg, pZ, nullptr, nullptr, 2048, 1024);
    // out = LN(sigmoid(Z)*ttt + (1-sigmoid(Z))*x)
    gate_ln_kernel<<<N_, 256>>>(pZ, pTT, x, gamma, beta, out);
}

// round 8
// speedup vs baseline: 2.7266x; 1.1901x over previous
#include <cuda_runtime.h>
#include <cuda_fp16.h>
#include <cstdint>
#include <math.h>

#define B_ 64
#define S_ 512
#define H_ 1024
#define I_ 1024
#define N_ (B_*S_)
#define SC (0.01f/1024.0f)
#define EPS_ 1e-5f

// ================= scratch =================
__device__ float  g_TE[(size_t)N_*2048];      // [T | A->E], ld=2048 (fp32)
__device__ float  g_ttt[(size_t)N_*H_];
__device__ float  g_Z[(size_t)N_*H_];
__device__ float  g_C[(size_t)B_*S_*S_];      // fp32 gram (+1)
__device__ __half g_Cs16[(size_t)B_*S_*S_];   // fp16(-SC * C)
__device__ float  g_Minv[(size_t)B_*8*64*64];
__device__ float  g_bcat[2048];
__device__ __half g_xh[(size_t)N_*H_];
__device__ __half g_xl[(size_t)N_*H_];
__device__ __half g_Sh[(size_t)N_*I_];        // EhT during solve, then silu hi
__device__ __half g_Sl[(size_t)N_*I_];
__device__ __half g_TTh[(size_t)N_*H_];
__device__ __half g_TTl[(size_t)N_*H_];
__device__ __half g_Bh[(size_t)2048*1024];    // [Wt | Winit-Wt]^T  [n=2048][k=1024]
__device__ __half g_Bl[(size_t)2048*1024];
__device__ __half g_Woh[(size_t)1024*1024];   // Wo^T
__device__ __half g_Wol[(size_t)1024*1024];
__device__ __half g_Wgh[(size_t)1024*2048];   // Wg^T [n=1024][k=2048]
__device__ __half g_Wgl[(size_t)1024*2048];

__constant__ int c_TI[10] = {0,1,1,2,2,2,3,3,3,3};
__constant__ int c_TJ[10] = {0,0,1,0,1,2,0,1,2,3};

// ================= helpers =================
__device__ __forceinline__ uint32_t smem_u32(const void* p) {
    uint32_t a;
    asm("{ .reg .u64 t; cvta.to.shared.u64 t, %1; cvt.u32.u64 %0, t; }" : "=r"(a) : "l"(p));
    return a;
}
__device__ __forceinline__ void hsplit(float v, __half& h, __half& l) {
    h = __float2half_rn(v);
    l = __float2half_rn(v - __half2float(h));
}
__device__ __forceinline__ float silu_f(float v) { return v / (1.0f + expf(-v)); }

__device__ __forceinline__ void ldm_x4(uint32_t* r, uint32_t addr) {
    asm volatile("ldmatrix.sync.aligned.m8n8.x4.shared.b16 {%0,%1,%2,%3}, [%4];"
        : "=r"(r[0]), "=r"(r[1]), "=r"(r[2]), "=r"(r[3]) : "r"(addr));
}
__device__ __forceinline__ void mma16816(float* d, const uint32_t* a, uint32_t b0, uint32_t b1) {
    asm volatile("mma.sync.aligned.m16n8k16.row.col.f32.f16.f16.f32 "
        "{%0,%1,%2,%3},{%4,%5,%6,%7},{%8,%9},{%0,%1,%2,%3};"
        : "+f"(d[0]), "+f"(d[1]), "+f"(d[2]), "+f"(d[3])
        : "r"(a[0]), "r"(a[1]), "r"(a[2]), "r"(a[3]), "r"(b0), "r"(b1));
}

// cp.async ROWS x 32-half tile (64B/row), XOR-swizzled 16B chunks; g pre-offset to (row0,k)
template<int ROWS>
__device__ __forceinline__ void cp_rows(__half* s, const __half* __restrict__ g,
                                        int ld, int tid) {
#pragma unroll
    for (int i = 0; i < ROWS / 64; i++) {
        int cid = tid + 256 * i;
        int row = cid >> 2, c = cid & 3;
        const __half* gp = g + (size_t)row * ld + c * 8;
        int sc = c ^ ((row >> 1) & 3);
        uint32_t d = smem_u32(s + row * 32 + sc * 8);
        asm volatile("cp.async.cg.shared.global [%0], [%1], 16;" :: "r"(d), "l"(gp));
    }
}

// ============ interleaved mma.sync fp16-3x GEMM ============
// MODE 0: C[M,N] = A@B^T + bias  (single K pass; per stage load Ah,Al,Bh,Bl)
// MODE 1: A = concat(A0,A1) along K (K=2048)
// MODE 2: gram 1-pass fp16-hi; EPI 2: write fp32 C(+1) and fp16(-SC*C)
// EPI 1: also write hi/lo fp16 split of C
template<int MODE, int EPI>
__global__ __launch_bounds__(256)
void gemm_mma(const __half* __restrict__ Ah0, const __half* __restrict__ Al0,
              const __half* __restrict__ Ah1, const __half* __restrict__ Al1,
              const __half* __restrict__ Bh, const __half* __restrict__ Bl,
              const float* __restrict__ bias,
              float* __restrict__ C, __half* __restrict__ Ch, __half* __restrict__ Cl,
              int ldb, int ldc)
{
    extern __shared__ __align__(16) __half smem[];
    constexpr int SSTRIDE = (MODE == 2) ? 8192 : 16384;   // halves per stage

    const int tid = threadIdx.x;
    const int warp = tid >> 5, lane = tid & 31;
    const int warpM = warp & 3, warpN = warp >> 2;   // 4 x 2 warps
    const int K = (MODE == 1) ? 2048 : 1024;
    const int NS = K >> 5;

    size_t arow, brow; int crow0, ccol0, ldcc; float* cb;
    if (MODE == 2) {
        const int b = blockIdx.y;
        crow0 = c_TI[blockIdx.x] << 7; ccol0 = c_TJ[blockIdx.x] << 7;
        arow = (size_t)b * S_ + crow0; brow = (size_t)b * S_ + ccol0;
        cb = C + (size_t)b * S_ * S_; ldcc = S_;
        Ch = Ch + (size_t)b * S_ * S_;
    } else {
        arow = (size_t)blockIdx.y << 7; brow = (size_t)blockIdx.x << 7;
        crow0 = (int)arow; ccol0 = (int)brow; cb = C; ldcc = ldc;
    }

#define LOAD_STAGE(s_) do { \
        const int s__ = (s_); const int k0_ = s__ << 5; \
        __half* st_ = smem + (s__ % 3) * SSTRIDE; \
        if (MODE == 2) { \
            cp_rows<128>(st_,        Ah0 + arow * 1024 + k0_, 1024, tid); \
            cp_rows<128>(st_ + 4096, Ah0 + brow * 1024 + k0_, 1024, tid); \
        } else { \
            const __half *ah_ = Ah0, *al_ = Al0; int ak_ = k0_; \
            if (MODE == 1 && k0_ >= 1024) { ah_ = Ah1; al_ = Al1; ak_ = k0_ - 1024; } \
            cp_rows<128>(st_,         ah_ + arow * 1024 + ak_, 1024, tid); \
            cp_rows<128>(st_ + 4096,  al_ + arow * 1024 + ak_, 1024, tid); \
            cp_rows<128>(st_ + 8192,  Bh + brow * (size_t)ldb + k0_, ldb, tid); \
            cp_rows<128>(st_ + 12288, Bl + brow * (size_t)ldb + k0_, ldb, tid); \
        } \
        asm volatile("cp.async.commit_group;" ::: "memory"); \
    } while (0)

    float acc[2][8][4];
#pragma unroll
    for (int mt = 0; mt < 2; mt++)
#pragma unroll
        for (int j = 0; j < 8; j++)
#pragma unroll
            for (int q = 0; q < 4; q++) acc[mt][j][q] = 0.0f;

    LOAD_STAGE(0);
    LOAD_STAGE(1);
    asm volatile("cp.async.wait_group 1;" ::: "memory");
    __syncthreads();

    for (int s = 0; s < NS; s++) {
        if (s + 2 < NS) LOAD_STAGE(s + 2);
        const __half* st = smem + (s % 3) * SSTRIDE;
        const __half* Ahs = st;
        const __half* Als = st + 4096;
        const __half* Bhs = st + ((MODE == 2) ? 4096 : 8192);
        const __half* Bls = st + 12288;
#pragma unroll
        for (int kk = 0; kk < 2; kk++) {
            const int q = lane >> 3, r = lane & 7;
            uint32_t af[2][4];
#pragma unroll
            for (int mt = 0; mt < 2; mt++) {
                const int row = warpM * 32 + mt * 16 + ((q & 1) ? 8 : 0) + r;
                const int c = kk * 2 + (q >> 1);
                ldm_x4(af[mt], smem_u32(Ahs + row * 32 + (c ^ ((row >> 1) & 3)) * 8));
            }
            uint32_t bf[4][4];
#pragma unroll
            for (int nt = 0; nt < 4; nt++) {
                const int row = warpN * 64 + nt * 16 + ((q >> 1) ? 8 : 0) + r;
                const int c = kk * 2 + (q & 1);
                ldm_x4(bf[nt], smem_u32(Bhs + row * 32 + (c ^ ((row >> 1) & 3)) * 8));
            }
#pragma unroll
            for (int mt = 0; mt < 2; mt++)
#pragma unroll
                for (int nt = 0; nt < 4; nt++) {
                    mma16816(acc[mt][nt * 2 + 0], af[mt], bf[nt][0], bf[nt][1]);
                    mma16816(acc[mt][nt * 2 + 1], af[mt], bf[nt][2], bf[nt][3]);
                }
            if (MODE != 2) {
                uint32_t al2[2][4];
#pragma unroll
                for (int mt = 0; mt < 2; mt++) {
                    const int row = warpM * 32 + mt * 16 + ((q & 1) ? 8 : 0) + r;
                    const int c = kk * 2 + (q >> 1);
                    ldm_x4(al2[mt], smem_u32(Als + row * 32 + (c ^ ((row >> 1) & 3)) * 8));
                }
#pragma unroll
                for (int mt = 0; mt < 2; mt++)
#pragma unroll
                    for (int nt = 0; nt < 4; nt++) {
                        mma16816(acc[mt][nt * 2 + 0], al2[mt], bf[nt][0], bf[nt][1]);
                        mma16816(acc[mt][nt * 2 + 1], al2[mt], bf[nt][2], bf[nt][3]);
                    }
                // reuse bf for Bl
#pragma unroll
                for (int nt = 0; nt < 4; nt++) {
                    const int row = warpN * 64 + nt * 16 + ((q >> 1) ? 8 : 0) + r;
                    const int c = kk * 2 + (q & 1);
                    ldm_x4(bf[nt], smem_u32(Bls + row * 32 + (c ^ ((row >> 1) & 3)) * 8));
                }
#pragma unroll
                for (int mt = 0; mt < 2; mt++)
#pragma unroll
                    for (int nt = 0; nt < 4; nt++) {
                        mma16816(acc[mt][nt * 2 + 0], af[mt], bf[nt][0], bf[nt][1]);
                        mma16816(acc[mt][nt * 2 + 1], af[mt], bf[nt][2], bf[nt][3]);
                    }
            }
        }
        if (s + 1 < NS) {
            if (s + 2 < NS) asm volatile("cp.async.wait_group 1;" ::: "memory");
            else            asm volatile("cp.async.wait_group 0;" ::: "memory");
            __syncthreads();
        }
    }
#undef LOAD_STAGE

    // epilogue
    const int baseRow = crow0 + warpM * 32;
    const int baseCol = ccol0 + warpN * 64;
#pragma unroll
    for (int mt = 0; mt < 2; mt++) {
#pragma unroll
        for (int j = 0; j < 8; j++) {
            const int col = baseCol + j * 8 + (lane & 3) * 2;
            const int r0 = baseRow + mt * 16 + (lane >> 2);
            float bx, by;
            if (MODE == 2) { bx = 1.0f; by = 1.0f; }
            else { bx = bias[col]; by = bias[col + 1]; }
            float v0 = acc[mt][j][0] + bx, v1 = acc[mt][j][1] + by;
            float v2 = acc[mt][j][2] + bx, v3 = acc[mt][j][3] + by;
            *reinterpret_cast<float2*>(cb + (size_t)r0 * ldcc + col) = make_float2(v0, v1);
            *reinterpret_cast<float2*>(cb + (size_t)(r0 + 8) * ldcc + col) = make_float2(v2, v3);
            if (EPI == 1) {
                __half h0, l0, h1, l1, h2, l2, h3, l3;
                hsplit(v0, h0, l0); hsplit(v1, h1, l1);
                hsplit(v2, h2, l2); hsplit(v3, h3, l3);
                *reinterpret_cast<__half2*>(Ch + (size_t)r0 * ldcc + col) = __halves2half2(h0, h1);
                *reinterpret_cast<__half2*>(Cl + (size_t)r0 * ldcc + col) = __halves2half2(l0, l1);
                *reinterpret_cast<__half2*>(Ch + (size_t)(r0 + 8) * ldcc + col) = __halves2half2(h2, h3);
                *reinterpret_cast<__half2*>(Cl + (size_t)(r0 + 8) * ldcc + col) = __halves2half2(l2, l3);
            }
            if (EPI == 2) {   // Cs16 = fp16(-SC * C)
                *reinterpret_cast<__half2*>(Ch + (size_t)r0 * ldcc + col) =
                    __halves2half2(__float2half_rn(-SC * v0), __float2half_rn(-SC * v1));
                *reinterpret_cast<__half2*>(Ch + (size_t)(r0 + 8) * ldcc + col) =
                    __halves2half2(__float2half_rn(-SC * v2), __float2half_rn(-SC * v3));
            }
        }
    }
}

// ================= prep kernels =================
__global__ void split_x_kernel(const float* __restrict__ x, __half* __restrict__ xh,
                               __half* __restrict__ xl) {
    size_t i = ((size_t)blockIdx.x * 256 + threadIdx.x) * 4;
    float4 v = *reinterpret_cast<const float4*>(x + i);
    __half h0, l0, h1, l1, h2, l2, h3, l3;
    hsplit(v.x, h0, l0); hsplit(v.y, h1, l1); hsplit(v.z, h2, l2); hsplit(v.w, h3, l3);
    *reinterpret_cast<__half2*>(xh + i)     = __halves2half2(h0, h1);
    *reinterpret_cast<__half2*>(xh + i + 2) = __halves2half2(h2, h3);
    *reinterpret_cast<__half2*>(xl + i)     = __halves2half2(l0, l1);
    *reinterpret_cast<__half2*>(xl + i + 2) = __halves2half2(l2, l3);
}

__global__ void tsplit_kernel(const float* __restrict__ W, const float* __restrict__ Wsub,
                              __half* __restrict__ oh, __half* __restrict__ ol,
                              int N, int ldo, int roff)
{
    __shared__ float t[32][33];
    const int k0 = blockIdx.x * 32, n0 = blockIdx.y * 32;
    const int tx = threadIdx.x, ty = threadIdx.y;
#pragma unroll
    for (int i = 0; i < 32; i += 8) {
        float v = W[(size_t)(k0 + ty + i) * N + n0 + tx];
        if (Wsub) v -= Wsub[(size_t)(k0 + ty + i) * N + n0 + tx];
        t[ty + i][tx] = v;
    }
    __syncthreads();
#pragma unroll
    for (int i = 0; i < 32; i += 8) {
        __half h, l;
        hsplit(t[tx][ty + i], h, l);
        oh[(size_t)(n0 + ty + i + roff) * ldo + k0 + tx] = h;
        ol[(size_t)(n0 + ty + i + roff) * ldo + k0 + tx] = l;
    }
}

__global__ void bcat_kernel(const float* __restrict__ bt, const float* __restrict__ bi,
                            float* __restrict__ bc) {
    int j = blockIdx.x * 256 + threadIdx.x;
    if (j < 1024) bc[j] = bt[j];
    else if (j < 2048) bc[j] = bi[j - 1024] - bt[j - 1024];
}

__global__ void silu_split_kernel(__half* __restrict__ Sh, __half* __restrict__ Sl) {
    size_t idx4 = (size_t)blockIdx.x * 256 + threadIdx.x;
    size_t r = idx4 >> 8, j4 = (idx4 & 255) * 4;
    size_t base = r * 2048 + j4;
    float4 t = *reinterpret_cast<const float4*>(g_TE + base);
    float4 e = *reinterpret_cast<const float4*>(g_TE + base + 1024);
    float s0 = silu_f(t.x + e.x), s1 = silu_f(t.y + e.y);
    float s2 = silu_f(t.z + e.z), s3 = silu_f(t.w + e.w);
    __half h0, l0, h1, l1, h2, l2, h3, l3;
    hsplit(s0, h0, l0); hsplit(s1, h1, l1); hsplit(s2, h2, l2); hsplit(s3, h3, l3);
    size_t ob = r * 1024 + j4;
    *reinterpret_cast<__half2*>(Sh + ob)     = __halves2half2(h0, h1);
    *reinterpret_cast<__half2*>(Sh + ob + 2) = __halves2half2(h2, h3);
    *reinterpret_cast<__half2*>(Sl + ob)     = __halves2half2(l0, l1);
    *reinterpret_cast<__half2*>(Sl + ob + 2) = __halves2half2(l2, l3);
}

// ================= triangular inverse per (batch, chunk) =================
__global__ __launch_bounds__(64) void tri_inv_kernel()
{
    __shared__ float L[64][65];
    __shared__ float Msm[64][65];
    const int bc = blockIdx.x, b = bc >> 3, ch = bc & 7;
    const int j = threadIdx.x;
    const float* Cb = g_C + (size_t)b * S_ * S_ + (size_t)(ch * 64) * S_ + ch * 64;
    for (int r = 0; r < 64; r++) L[r][j] = Cb[(size_t)r * S_ + j];
    for (int t = 0; t < 64; t++) Msm[t][j] = (t == j) ? 1.0f : 0.0f;
    __syncthreads();
    for (int t = 1; t < 64; t++) {
        if (t > j) {
            float a = 0.0f;
            for (int s = j; s < t; s++) a += L[t][s] * Msm[s][j];
            Msm[t][j] = -SC * a;
        }
    }
    float* Mo = g_Minv + (size_t)bc * 64 * 64;
    for (int r = 0; r < 64; r++) Mo[r * 64 + j] = Msm[r][j];
}

// ================= mma-based chunk solve =================
// Per (b, colblk): acc = sum_pc (-sc*C[ch,pc]) @ Eh[pc]   (fp16 mma, K=64*ch)
// R = A + acc ;  E = Minv @ R (SIMT) ; write E to TE fp32 and EhT fp16.
__global__ __launch_bounds__(256) void solve_mma_kernel(int ch)
{
    extern __shared__ __align__(16) char sm[];
    __half* As0 = (__half*)sm;            // 64x32
    __half* As1 = As0 + 2048;
    __half* Bs0 = As1 + 2048;             // 128x32
    __half* Bs1 = Bs0 + 4096;
    float*  Rf  = (float*)(Bs1 + 4096);   // [64][132]
    float*  Ms  = Rf + 64 * 132;          // [64][65]

    const int tid = threadIdx.x;
    const int warp = tid >> 5, lane = tid & 31;
    const int warpM = warp & 3, warpN = warp >> 2;   // 4 row-groups x 2 col-groups
    const int b = blockIdx.y;
    const int col0 = blockIdx.x << 7;
    float* Eb = g_TE + (size_t)b * S_ * 2048 + 1024;
    const __half* Cs = g_Cs16 + (size_t)b * S_ * S_ + (size_t)(ch * 64) * S_;
    __half* EhT = g_Sh + (size_t)b * 1024 * 512;

    float acc[8][4];
#pragma unroll
    for (int nt = 0; nt < 8; nt++)
#pragma unroll
        for (int q = 0; q < 4; q++) acc[nt][q] = 0.0f;

    for (int pc = 0; pc < ch; pc++) {
        cp_rows<64>(As0, Cs + pc * 64, S_, tid);
        cp_rows<64>(As1, Cs + pc * 64 + 32, S_, tid);
        cp_rows<128>(Bs0, EhT + (size_t)col0 * 512 + pc * 64, 512, tid);
        cp_rows<128>(Bs1, EhT + (size_t)col0 * 512 + pc * 64 + 32, 512, tid);
        asm volatile("cp.async.commit_group;" ::: "memory");
        asm volatile("cp.async.wait_group 0;" ::: "memory");
        __syncthreads();
#pragma unroll
        for (int kk = 0; kk < 4; kk++) {
            const __half* As = (kk < 2) ? As0 : As1;
            const __half* Bs = (kk < 2) ? Bs0 : Bs1;
            const int kl = kk & 1;
            const int q = lane >> 3, r = lane & 7;
            uint32_t af[4];
            {
                const int row = warpM * 16 + ((q & 1) ? 8 : 0) + r;
                const int c = kl * 2 + (q >> 1);
                ldm_x4(af, smem_u32(As + row * 32 + (c ^ ((row >> 1) & 3)) * 8));
            }
            uint32_t bf[4][4];
#pragma unroll
            for (int ntc = 0; ntc < 4; ntc++) {
                const int row = warpN * 64 + ntc * 16 + ((q >> 1) ? 8 : 0) + r;
                const int c = kl * 2 + (q & 1);
                ldm_x4(bf[ntc], smem_u32(Bs + row * 32 + (c ^ ((row >> 1) & 3)) * 8));
            }
#pragma unroll
            for (int ntc = 0; ntc < 4; ntc++) {
                mma16816(acc[ntc * 2 + 0], af, bf[ntc][0], bf[ntc][1]);
                mma16816(acc[ntc * 2 + 1], af, bf[ntc][2], bf[ntc][3]);
            }
        }
        __syncthreads();
    }

    // load Minv into smem (start early)
    const float* Mo = g_Minv + (size_t)(b * 8 + ch) * 4096;
    for (int idx = tid; idx < 4096; idx += 256)
        Ms[(idx >> 6) * 65 + (idx & 63)] = Mo[idx];

    // R = A + acc -> Rf smem
    {
        const int r0 = warpM * 16 + (lane >> 2);
        const float* Arow = Eb + (size_t)(ch * 64) * 2048 + col0;
#pragma unroll
        for (int nt = 0; nt < 8; nt++) {
            const int col = warpN * 64 + nt * 8 + (lane & 3) * 2;
            float2 a0 = *reinterpret_cast<const float2*>(Arow + (size_t)r0 * 2048 + col);
            float2 a1 = *reinterpret_cast<const float2*>(Arow + (size_t)(r0 + 8) * 2048 + col);
            Rf[r0 * 132 + col]           = a0.x + acc[nt][0];
            Rf[r0 * 132 + col + 1]       = a0.y + acc[nt][1];
            Rf[(r0 + 8) * 132 + col]     = a1.x + acc[nt][2];
            Rf[(r0 + 8) * 132 + col + 1] = a1.y + acc[nt][3];
        }
    }
    __syncthreads();

    // E = Minv @ R (SIMT, K=64), write TE fp32 + EhT fp16
    const int ty = tid >> 4, tx = tid & 15;   // rows ty*4..+4, cols tx*8..+8
    float e[4][8];
#pragma unroll
    for (int rr = 0; rr < 4; rr++)
#pragma unroll
        for (int cc = 0; cc < 8; cc++) e[rr][cc] = 0.0f;
    for (int qq = 0; qq < 64; qq++) {
        float mv[4];
#pragma unroll
        for (int rr = 0; rr < 4; rr++) mv[rr] = Ms[(ty * 4 + rr) * 65 + qq];
        float4 rv0 = *reinterpret_cast<const float4*>(&Rf[qq * 132 + tx * 8]);
        float4 rv1 = *reinterpret_cast<const float4*>(&Rf[qq * 132 + tx * 8 + 4]);
#pragma unroll
        for (int rr = 0; rr < 4; rr++) {
            e[rr][0] += mv[rr] * rv0.x; e[rr][1] += mv[rr] * rv0.y;
            e[rr][2] += mv[rr] * rv0.z; e[rr][3] += mv[rr] * rv0.w;
            e[rr][4] += mv[rr] * rv1.x; e[rr][5] += mv[rr] * rv1.y;
            e[rr][6] += mv[rr] * rv1.z; e[rr][7] += mv[rr] * rv1.w;
        }
    }
#pragma unroll
    for (int rr = 0; rr < 4; rr++) {
        const int row = ch * 64 + ty * 4 + rr;
        *reinterpret_cast<float4*>(Eb + (size_t)row * 2048 + col0 + tx * 8) =
            make_float4(e[rr][0], e[rr][1], e[rr][2], e[rr][3]);
        *reinterpret_cast<float4*>(Eb + (size_t)row * 2048 + col0 + tx * 8 + 4) =
            make_float4(e[rr][4], e[rr][5], e[rr][6], e[rr][7]);
    }
#pragma unroll
    for (int cc = 0; cc < 8; cc++) {
        const int gcol = col0 + tx * 8 + cc;
        __half2 p0 = __halves2half2(__float2half_rn(e[0][cc]), __float2half_rn(e[1][cc]));
        __half2 p1 = __halves2half2(__float2half_rn(e[2][cc]), __float2half_rn(e[3][cc]));
        *reinterpret_cast<__half2*>(EhT + (size_t)gcol * 512 + ch * 64 + ty * 4)     = p0;
        *reinterpret_cast<__half2*>(EhT + (size_t)gcol * 512 + ch * 64 + ty * 4 + 2) = p1;
    }
}

// ================= fused sigmoid-gate + LayerNorm =================
__global__ __launch_bounds__(256) void gate_ln_kernel(
    const float* __restrict__ Z, const float* __restrict__ T, const float* __restrict__ X,
    const float* __restrict__ gamma, const float* __restrict__ beta, float* __restrict__ out)
{
    __shared__ float red[16];
    __shared__ float mu_s, rinv_s;
    const int n = blockIdx.x, tid = threadIdx.x;
    const size_t base = (size_t)n * H_ + tid * 4;
    float4 z = *(const float4*)(Z + base);
    float4 t = *(const float4*)(T + base);
    float4 x = *(const float4*)(X + base);
    float h[4];
    {
        float g;
        g = 1.0f / (1.0f + expf(-z.x)); h[0] = g * t.x + (1.0f - g) * x.x;
        g = 1.0f / (1.0f + expf(-z.y)); h[1] = g * t.y + (1.0f - g) * x.y;
        g = 1.0f / (1.0f + expf(-z.z)); h[2] = g * t.z + (1.0f - g) * x.z;
        g = 1.0f / (1.0f + expf(-z.w)); h[3] = g * t.w + (1.0f - g) * x.w;
    }
    float s = h[0] + h[1] + h[2] + h[3];
    float q = h[0]*h[0] + h[1]*h[1] + h[2]*h[2] + h[3]*h[3];
#pragma unroll
    for (int o = 16; o > 0; o >>= 1) {
        s += __shfl_xor_sync(0xffffffffu, s, o);
        q += __shfl_xor_sync(0xffffffffu, q, o);
    }
    const int lane = tid & 31, wid = tid >> 5;
    if (lane == 0) { red[wid] = s; red[8 + wid] = q; }
    __syncthreads();
    if (tid == 0) {
        float Sa = 0.0f, Q = 0.0f;
#pragma unroll
        for (int w = 0; w < 8; w++) { Sa += red[w]; Q += red[8 + w]; }
        float mu = Sa * (1.0f / H_);
        mu_s = mu; rinv_s = rsqrtf(Q * (1.0f / H_) - mu * mu + EPS_);
    }
    __syncthreads();
    const float mu = mu_s, rinv = rinv_s;
    float4 gm = *(const float4*)(gamma + tid * 4);
    float4 bt = *(const float4*)(beta + tid * 4);
    float4 o;
    o.x = (h[0] - mu) * rinv * gm.x + bt.x;
    o.y = (h[1] - mu) * rinv * gm.y + bt.y;
    o.z = (h[2] - mu) * rinv * gm.z + bt.z;
    o.w = (h[3] - mu) * rinv * gm.w + bt.w;
    *(float4*)(out + base) = o;
}

// ================= launch =================
extern "C" void kernel_launch(void* const* d_in, const int* in_sizes, int n_in,
                              void* d_out, int out_size)
{
    const float* x      = (const float*)d_in[0];
    const float* W_init = (const float*)d_in[1];
    const float* b_init = (const float*)d_in[2];
    const float* Wt     = (const float*)d_in[3];
    const float* bt     = (const float*)d_in[4];
    const float* Wo     = (const float*)d_in[5];
    const float* bo     = (const float*)d_in[6];
    const float* Wg     = (const float*)d_in[7];
    const float* bg     = (const float*)d_in[8];
    const float* gamma  = (const float*)d_in[9];
    const float* beta   = (const float*)d_in[10];
    float* out = (float*)d_out;

    float *pTE, *pTT, *pZ, *pC, *pbc;
    __half *pxh, *pxl, *pSh, *pSl, *pTTh, *pTTl, *pBh, *pBl, *pWoh, *pWol, *pWgh, *pWgl, *pCs;
    cudaGetSymbolAddress((void**)&pTE,  g_TE);
    cudaGetSymbolAddress((void**)&pTT,  g_ttt);
    cudaGetSymbolAddress((void**)&pZ,   g_Z);
    cudaGetSymbolAddress((void**)&pC,   g_C);
    cudaGetSymbolAddress((void**)&pCs,  g_Cs16);
    cudaGetSymbolAddress((void**)&pbc,  g_bcat);
    cudaGetSymbolAddress((void**)&pxh,  g_xh);
    cudaGetSymbolAddress((void**)&pxl,  g_xl);
    cudaGetSymbolAddress((void**)&pSh,  g_Sh);
    cudaGetSymbolAddress((void**)&pSl,  g_Sl);
    cudaGetSymbolAddress((void**)&pTTh, g_TTh);
    cudaGetSymbolAddress((void**)&pTTl, g_TTl);
    cudaGetSymbolAddress((void**)&pBh,  g_Bh);
    cudaGetSymbolAddress((void**)&pBl,  g_Bl);
    cudaGetSymbolAddress((void**)&pWoh, g_Woh);
    cudaGetSymbolAddress((void**)&pWol, g_Wol);
    cudaGetSymbolAddress((void**)&pWgh, g_Wgh);
    cudaGetSymbolAddress((void**)&pWgl, g_Wgl);

    const int SMB  = 3 * 16384 * 2;   // 98304 B: 3 stages x (Ah,Al,Bh,Bl)
    const int SMG  = 3 * 8192 * 2;    // 49152 B: gram
    const int SMS  = 24576 + 64 * 132 * 4 + 64 * 65 * 4;   // solve: ~75 KB
    cudaFuncSetAttribute(gemm_mma<0,0>, cudaFuncAttributeMaxDynamicSharedMemorySize, SMB);
    cudaFuncSetAttribute(gemm_mma<0,1>, cudaFuncAttributeMaxDynamicSharedMemorySize, SMB);
    cudaFuncSetAttribute(gemm_mma<1,0>, cudaFuncAttributeMaxDynamicSharedMemorySize, SMB);
    cudaFuncSetAttribute(gemm_mma<2,2>, cudaFuncAttributeMaxDynamicSharedMemorySize, SMG);
    cudaFuncSetAttribute(solve_mma_kernel, cudaFuncAttributeMaxDynamicSharedMemorySize, SMS);

    dim3 tb(32, 8);
    split_x_kernel<<<N_ * H_ / 1024, 256>>>(x, pxh, pxl);
    tsplit_kernel<<<dim3(32, 32), tb>>>(Wt, nullptr, pBh, pBl, 1024, 1024, 0);
    tsplit_kernel<<<dim3(32, 32), tb>>>(W_init, Wt, pBh, pBl, 1024, 1024, 1024);
    tsplit_kernel<<<dim3(32, 32), tb>>>(Wo, nullptr, pWoh, pWol, 1024, 1024, 0);
    tsplit_kernel<<<dim3(64, 32), tb>>>(Wg, nullptr, pWgh, pWgl, 1024, 2048, 0);
    bcat_kernel<<<8, 256>>>(bt, b_init, pbc);

    // [T | A] = x @ [Wt | Winit-Wt] + [bt | binit-bt]  (N=2048)
    gemm_mma<0,0><<<dim3(16, 256), 256, SMB>>>(pxh, pxl, nullptr, nullptr,
                                               pBh, pBl, pbc, pTE, nullptr, nullptr, 1024, 2048);
    // Gram lower tiles: fp32 C(+1) and fp16(-SC*C)
    gemm_mma<2,2><<<dim3(10, 64), 256, SMG>>>(pxh, nullptr, nullptr, nullptr,
                                              nullptr, nullptr, nullptr, pC, pCs, nullptr,
                                              1024, 0);
    tri_inv_kernel<<<512, 64>>>();
    for (int ch = 0; ch < 8; ch++)
        solve_mma_kernel<<<dim3(8, 64), 256, SMS>>>(ch);
    // S = silu(T + E), fp16 split (overwrites EhT in g_Sh)
    silu_split_kernel<<<N_ * H_ / 1024, 256>>>(pSh, pSl);
    // ttt = S @ Wo + bo (EPI writes fp16 split too)
    gemm_mma<0,1><<<dim3(8, 256), 256, SMB>>>(pSh, pSl, nullptr, nullptr,
                                              pWoh, pWol, bo, pTT, pTTh, pTTl, 1024, 1024);
    // Z = [x, ttt] @ Wg + bg
    gemm_mma<1,0><<<dim3(8, 256), 256, SMB>>>(pxh, pxl, pTTh, pTTl,
                                              pWgh, pWgl, bg, pZ, nullptr, nullptr, 2048, 1024);
    // out = LN(sigmoid(Z)*ttt + (1-sigmoid(Z))*x)
    gate_ln_kernel<<<N_, 256>>>(pZ, pTT, x, gamma, beta, out);
}

// round 10
// speedup vs baseline: 3.8351x; 1.4065x over previous
#include <cuda_runtime.h>
#include <cuda_fp16.h>
#include <cstdint>
#include <math.h>

#define B_ 64
#define S_ 512
#define H_ 1024
#define I_ 1024
#define N_ (B_*S_)
#define SC (0.01f/1024.0f)
#define EPS_ 1e-5f

// ================= scratch =================
__device__ float  g_TE[(size_t)N_*2048];      // [T | A->E], ld=2048 (fp32)
__device__ float  g_ttt[(size_t)N_*H_];
__device__ float  g_Z[(size_t)N_*H_];
__device__ float  g_C[(size_t)B_*S_*S_];      // fp32 gram (+1)
__device__ __half g_Cs16[(size_t)B_*S_*S_];   // fp16(-SC * C)
__device__ float  g_Minv[(size_t)B_*8*64*64];
__device__ float  g_bcat[2048];
__device__ __half g_xh[(size_t)N_*H_];
__device__ __half g_Sh[(size_t)N_*I_];        // EhT during solve, then silu hi
__device__ __half g_TTh[(size_t)N_*H_];
__device__ __half g_Bh[(size_t)2048*1024];    // [Wt | Winit-Wt]^T  [n=2048][k=1024]
__device__ __half g_Bl[(size_t)2048*1024];
__device__ __half g_Woh[(size_t)1024*1024];   // Wo^T
__device__ __half g_Wol[(size_t)1024*1024];
__device__ __half g_Wgh[(size_t)1024*2048];   // Wg^T [n=1024][k=2048]
__device__ __half g_Wgl[(size_t)1024*2048];

__constant__ int c_TI[10] = {0,1,1,2,2,2,3,3,3,3};
__constant__ int c_TJ[10] = {0,0,1,0,1,2,0,1,2,3};

// ================= helpers =================
__device__ __forceinline__ uint32_t smem_u32(const void* p) {
    uint32_t a;
    asm("{ .reg .u64 t; cvta.to.shared.u64 t, %1; cvt.u32.u64 %0, t; }" : "=r"(a) : "l"(p));
    return a;
}
__device__ __forceinline__ void hsplit(float v, __half& h, __half& l) {
    h = __float2half_rn(v);
    l = __float2half_rn(v - __half2float(h));
}
__device__ __forceinline__ float silu_f(float v) { return v / (1.0f + expf(-v)); }

__device__ __forceinline__ void ldm_x4(uint32_t* r, uint32_t addr) {
    asm volatile("ldmatrix.sync.aligned.m8n8.x4.shared.b16 {%0,%1,%2,%3}, [%4];"
        : "=r"(r[0]), "=r"(r[1]), "=r"(r[2]), "=r"(r[3]) : "r"(addr));
}
__device__ __forceinline__ void mma16816(float* d, const uint32_t* a, uint32_t b0, uint32_t b1) {
    asm volatile("mma.sync.aligned.m16n8k16.row.col.f32.f16.f16.f32 "
        "{%0,%1,%2,%3},{%4,%5,%6,%7},{%8,%9},{%0,%1,%2,%3};"
        : "+f"(d[0]), "+f"(d[1]), "+f"(d[2]), "+f"(d[3])
        : "r"(a[0]), "r"(a[1]), "r"(a[2]), "r"(a[3]), "r"(b0), "r"(b1));
}

// cp.async ROWS x 32-half tile (64B/row), XOR-swizzled 16B chunks; g pre-offset to (row0,k)
template<int ROWS>
__device__ __forceinline__ void cp_rows(__half* s, const __half* __restrict__ g,
                                        int ld, int tid) {
#pragma unroll
    for (int i = 0; i < ROWS / 64; i++) {
        int cid = tid + 256 * i;
        int row = cid >> 2, c = cid & 3;
        const __half* gp = g + (size_t)row * ld + c * 8;
        int sc = c ^ ((row >> 1) & 3);
        uint32_t d = smem_u32(s + row * 32 + sc * 8);
        asm volatile("cp.async.cg.shared.global [%0], [%1], 16;" :: "r"(d), "l"(gp));
    }
}

// ============ 2-term mma.sync GEMM: C = Ah@(Bh+Bl)^T + bias ============
// MODE 0: A = Ah0 [M,1024]
// MODE 1: A = concat(Ah0, Ah1) along K (K=2048)
// MODE 2: gram (1-term): per-batch lower tiles of x x^T + 1
// EPI 1: also write fp16(C) to Ch;  EPI 2 (gram): write fp32 C(+1) and Ch=fp16(-SC*C)
template<int MODE, int EPI>
__global__ __launch_bounds__(256, 2)
void gemm_mma(const __half* __restrict__ Ah0, const __half* __restrict__ Ah1,
              const __half* __restrict__ Bh, const __half* __restrict__ Bl,
              const float* __restrict__ bias,
              float* __restrict__ C, __half* __restrict__ Ch,
              int ldb, int ldc)
{
    extern __shared__ __align__(16) __half smem[];
    constexpr int SSTRIDE = (MODE == 2) ? 8192 : 12288;   // halves per stage

    const int tid = threadIdx.x;
    const int warp = tid >> 5, lane = tid & 31;
    const int warpM = warp & 3, warpN = warp >> 2;   // 4 x 2 warps (32x64 each)
    const int K = (MODE == 1) ? 2048 : 1024;
    const int NS = K >> 5;

    size_t arow, brow; int crow0, ccol0, ldcc; float* cb;
    if (MODE == 2) {
        const int b = blockIdx.y;
        crow0 = c_TI[blockIdx.x] << 7; ccol0 = c_TJ[blockIdx.x] << 7;
        arow = (size_t)b * S_ + crow0; brow = (size_t)b * S_ + ccol0;
        cb = C + (size_t)b * S_ * S_; ldcc = S_;
        Ch = Ch + (size_t)b * S_ * S_;
    } else {
        arow = (size_t)blockIdx.y << 7; brow = (size_t)blockIdx.x << 7;
        crow0 = (int)arow; ccol0 = (int)brow; cb = C; ldcc = ldc;
    }

#define LOAD_STAGE(s_) do { \
        const int s__ = (s_); const int k0_ = s__ << 5; \
        __half* st_ = smem + (s__ & 1) * SSTRIDE; \
        if (MODE == 2) { \
            cp_rows<128>(st_,        Ah0 + arow * 1024 + k0_, 1024, tid); \
            cp_rows<128>(st_ + 4096, Ah0 + brow * 1024 + k0_, 1024, tid); \
        } else { \
            const __half* ah_ = Ah0; int ak_ = k0_; \
            if (MODE == 1 && k0_ >= 1024) { ah_ = Ah1; ak_ = k0_ - 1024; } \
            cp_rows<128>(st_,        ah_ + arow * 1024 + ak_, 1024, tid); \
            cp_rows<128>(st_ + 4096, Bh + brow * (size_t)ldb + k0_, ldb, tid); \
            cp_rows<128>(st_ + 8192, Bl + brow * (size_t)ldb + k0_, ldb, tid); \
        } \
        asm volatile("cp.async.commit_group;" ::: "memory"); \
    } while (0)

    float acc[2][8][4];
#pragma unroll
    for (int mt = 0; mt < 2; mt++)
#pragma unroll
        for (int j = 0; j < 8; j++)
#pragma unroll
            for (int q = 0; q < 4; q++) acc[mt][j][q] = 0.0f;

    LOAD_STAGE(0);
    LOAD_STAGE(1);

    for (int s = 0; s < NS; s++) {
        if (s == NS - 1) asm volatile("cp.async.wait_group 0;" ::: "memory");
        else             asm volatile("cp.async.wait_group 1;" ::: "memory");
        __syncthreads();
        const __half* st = smem + (s & 1) * SSTRIDE;
        const __half* Ahs = st;
        const __half* Bhs = st + 4096;
        const __half* Bls = st + 8192;
#pragma unroll
        for (int kk = 0; kk < 2; kk++) {
            const int q = lane >> 3, r = lane & 7;
            uint32_t af[2][4];
#pragma unroll
            for (int mt = 0; mt < 2; mt++) {
                const int row = warpM * 32 + mt * 16 + ((q & 1) ? 8 : 0) + r;
                const int c = kk * 2 + (q >> 1);
                ldm_x4(af[mt], smem_u32(Ahs + row * 32 + (c ^ ((row >> 1) & 3)) * 8));
            }
            uint32_t bf[4][4];
#pragma unroll
            for (int nt = 0; nt < 4; nt++) {
                const int row = warpN * 64 + nt * 16 + ((q >> 1) ? 8 : 0) + r;
                const int c = kk * 2 + (q & 1);
                ldm_x4(bf[nt], smem_u32(Bhs + row * 32 + (c ^ ((row >> 1) & 3)) * 8));
            }
#pragma unroll
            for (int mt = 0; mt < 2; mt++)
#pragma unroll
                for (int nt = 0; nt < 4; nt++) {
                    mma16816(acc[mt][nt * 2 + 0], af[mt], bf[nt][0], bf[nt][1]);
                    mma16816(acc[mt][nt * 2 + 1], af[mt], bf[nt][2], bf[nt][3]);
                }
            if (MODE != 2) {
#pragma unroll
                for (int nt = 0; nt < 4; nt++) {
                    const int row = warpN * 64 + nt * 16 + ((q >> 1) ? 8 : 0) + r;
                    const int c = kk * 2 + (q & 1);
                    ldm_x4(bf[nt], smem_u32(Bls + row * 32 + (c ^ ((row >> 1) & 3)) * 8));
                }
#pragma unroll
                for (int mt = 0; mt < 2; mt++)
#pragma unroll
                    for (int nt = 0; nt < 4; nt++) {
                        mma16816(acc[mt][nt * 2 + 0], af[mt], bf[nt][0], bf[nt][1]);
                        mma16816(acc[mt][nt * 2 + 1], af[mt], bf[nt][2], bf[nt][3]);
                    }
            }
        }
        if (s + 2 < NS) {
            __syncthreads();
            LOAD_STAGE(s + 2);
        }
    }
#undef LOAD_STAGE

    // epilogue
    const int baseRow = crow0 + warpM * 32;
    const int baseCol = ccol0 + warpN * 64;
#pragma unroll
    for (int mt = 0; mt < 2; mt++) {
#pragma unroll
        for (int j = 0; j < 8; j++) {
            const int col = baseCol + j * 8 + (lane & 3) * 2;
            const int r0 = baseRow + mt * 16 + (lane >> 2);
            float bx, by;
            if (MODE == 2) { bx = 1.0f; by = 1.0f; }
            else { bx = bias[col]; by = bias[col + 1]; }
            float v0 = acc[mt][j][0] + bx, v1 = acc[mt][j][1] + by;
            float v2 = acc[mt][j][2] + bx, v3 = acc[mt][j][3] + by;
            *reinterpret_cast<float2*>(cb + (size_t)r0 * ldcc + col) = make_float2(v0, v1);
            *reinterpret_cast<float2*>(cb + (size_t)(r0 + 8) * ldcc + col) = make_float2(v2, v3);
            if (EPI == 1) {
                *reinterpret_cast<__half2*>(Ch + (size_t)r0 * ldcc + col) =
                    __halves2half2(__float2half_rn(v0), __float2half_rn(v1));
                *reinterpret_cast<__half2*>(Ch + (size_t)(r0 + 8) * ldcc + col) =
                    __halves2half2(__float2half_rn(v2), __float2half_rn(v3));
            }
            if (EPI == 2) {   // Cs16 = fp16(-SC * C)
                *reinterpret_cast<__half2*>(Ch + (size_t)r0 * ldcc + col) =
                    __halves2half2(__float2half_rn(-SC * v0), __float2half_rn(-SC * v1));
                *reinterpret_cast<__half2*>(Ch + (size_t)(r0 + 8) * ldcc + col) =
                    __halves2half2(__float2half_rn(-SC * v2), __float2half_rn(-SC * v3));
            }
        }
    }
}

// ================= prep kernels =================
__global__ void conv_x_kernel(const float* __restrict__ x, __half* __restrict__ xh) {
    size_t i = ((size_t)blockIdx.x * 256 + threadIdx.x) * 4;
    float4 v = *reinterpret_cast<const float4*>(x + i);
    *reinterpret_cast<__half2*>(xh + i) =
        __halves2half2(__float2half_rn(v.x), __float2half_rn(v.y));
    *reinterpret_cast<__half2*>(xh + i + 2) =
        __halves2half2(__float2half_rn(v.z), __float2half_rn(v.w));
}

__global__ void tsplit_kernel(const float* __restrict__ W, const float* __restrict__ Wsub,
                              __half* __restrict__ oh, __half* __restrict__ ol,
                              int N, int ldo, int roff)
{
    __shared__ float t[32][33];
    const int k0 = blockIdx.x * 32, n0 = blockIdx.y * 32;
    const int tx = threadIdx.x, ty = threadIdx.y;
#pragma unroll
    for (int i = 0; i < 32; i += 8) {
        float v = W[(size_t)(k0 + ty + i) * N + n0 + tx];
        if (Wsub) v -= Wsub[(size_t)(k0 + ty + i) * N + n0 + tx];
        t[ty + i][tx] = v;
    }
    __syncthreads();
#pragma unroll
    for (int i = 0; i < 32; i += 8) {
        __half h, l;
        hsplit(t[tx][ty + i], h, l);
        oh[(size_t)(n0 + ty + i + roff) * ldo + k0 + tx] = h;
        ol[(size_t)(n0 + ty + i + roff) * ldo + k0 + tx] = l;
    }
}

__global__ void bcat_kernel(const float* __restrict__ bt, const float* __restrict__ bi,
                            float* __restrict__ bc) {
    int j = blockIdx.x * 256 + threadIdx.x;
    if (j < 1024) bc[j] = bt[j];
    else if (j < 2048) bc[j] = bi[j - 1024] - bt[j - 1024];
}

// S = silu(T + E) from g_TE (ld 2048) -> fp16 (ld 1024)
__global__ void silu_h_kernel(__half* __restrict__ Sh) {
    size_t idx4 = (size_t)blockIdx.x * 256 + threadIdx.x;
    size_t r = idx4 >> 8, j4 = (idx4 & 255) * 4;
    size_t base = r * 2048 + j4;
    float4 t = *reinterpret_cast<const float4*>(g_TE + base);
    float4 e = *reinterpret_cast<const float4*>(g_TE + base + 1024);
    float s0 = silu_f(t.x + e.x), s1 = silu_f(t.y + e.y);
    float s2 = silu_f(t.z + e.z), s3 = silu_f(t.w + e.w);
    size_t ob = r * 1024 + j4;
    *reinterpret_cast<__half2*>(Sh + ob) =
        __halves2half2(__float2half_rn(s0), __float2half_rn(s1));
    *reinterpret_cast<__half2*>(Sh + ob + 2) =
        __halves2half2(__float2half_rn(s2), __float2half_rn(s3));
}

// ================= triangular inverse per (batch, chunk) =================
__global__ __launch_bounds__(64) void tri_inv_kernel()
{
    __shared__ float L[64][65];
    __shared__ float Msm[64][65];
    const int bc = blockIdx.x, b = bc >> 3, ch = bc & 7;
    const int j = threadIdx.x;
    const float* Cb = g_C + (size_t)b * S_ * S_ + (size_t)(ch * 64) * S_ + ch * 64;
    for (int r = 0; r < 64; r++) L[r][j] = Cb[(size_t)r * S_ + j];
    for (int t = 0; t < 64; t++) Msm[t][j] = (t == j) ? 1.0f : 0.0f;
    __syncthreads();
    for (int t = 1; t < 64; t++) {
        if (t > j) {
            float a = 0.0f;
            for (int s = j; s < t; s++) a += L[t][s] * Msm[s][j];
            Msm[t][j] = -SC * a;
        }
    }
    float* Mo = g_Minv + (size_t)bc * 64 * 64;
    for (int r = 0; r < 64; r++) Mo[r * 64 + j] = Msm[r][j];
}

// ================= mma-based chunk solve =================
__global__ __launch_bounds__(256) void solve_mma_kernel(int ch)
{
    extern __shared__ __align__(16) char sm[];
    __half* As0 = (__half*)sm;            // 64x32
    __half* As1 = As0 + 2048;
    __half* Bs0 = As1 + 2048;             // 128x32
    __half* Bs1 = Bs0 + 4096;
    float*  Rf  = (float*)(Bs1 + 4096);   // [64][132]
    float*  Ms  = Rf + 64 * 132;          // [64][65]

    const int tid = threadIdx.x;
    const int warp = tid >> 5, lane = tid & 31;
    const int warpM = warp & 3, warpN = warp >> 2;
    const int b = blockIdx.y;
    const int col0 = blockIdx.x << 7;
    float* Eb = g_TE + (size_t)b * S_ * 2048 + 1024;
    const __half* Cs = g_Cs16 + (size_t)b * S_ * S_ + (size_t)(ch * 64) * S_;
    __half* EhT = g_Sh + (size_t)b * 1024 * 512;

    float acc[8][4];
#pragma unroll
    for (int nt = 0; nt < 8; nt++)
#pragma unroll
        for (int q = 0; q < 4; q++) acc[nt][q] = 0.0f;

    for (int pc = 0; pc < ch; pc++) {
        cp_rows<64>(As0, Cs + pc * 64, S_, tid);
        cp_rows<64>(As1, Cs + pc * 64 + 32, S_, tid);
        cp_rows<128>(Bs0, EhT + (size_t)col0 * 512 + pc * 64, 512, tid);
        cp_rows<128>(Bs1, EhT + (size_t)col0 * 512 + pc * 64 + 32, 512, tid);
        asm volatile("cp.async.commit_group;" ::: "memory");
        asm volatile("cp.async.wait_group 0;" ::: "memory");
        __syncthreads();
#pragma unroll
        for (int kk = 0; kk < 4; kk++) {
            const __half* As = (kk < 2) ? As0 : As1;
            const __half* Bs = (kk < 2) ? Bs0 : Bs1;
            const int kl = kk & 1;
            const int q = lane >> 3, r = lane & 7;
            uint32_t af[4];
            {
                const int row = warpM * 16 + ((q & 1) ? 8 : 0) + r;
                const int c = kl * 2 + (q >> 1);
                ldm_x4(af, smem_u32(As + row * 32 + (c ^ ((row >> 1) & 3)) * 8));
            }
            uint32_t bf[4][4];
#pragma unroll
            for (int ntc = 0; ntc < 4; ntc++) {
                const int row = warpN * 64 + ntc * 16 + ((q >> 1) ? 8 : 0) + r;
                const int c = kl * 2 + (q & 1);
                ldm_x4(bf[ntc], smem_u32(Bs + row * 32 + (c ^ ((row >> 1) & 3)) * 8));
            }
#pragma unroll
            for (int ntc = 0; ntc < 4; ntc++) {
                mma16816(acc[ntc * 2 + 0], af, bf[ntc][0], bf[ntc][1]);
                mma16816(acc[ntc * 2 + 1], af, bf[ntc][2], bf[ntc][3]);
            }
        }
        __syncthreads();
    }

    const float* Mo = g_Minv + (size_t)(b * 8 + ch) * 4096;
    for (int idx = tid; idx < 4096; idx += 256)
        Ms[(idx >> 6) * 65 + (idx & 63)] = Mo[idx];

    {
        const int r0 = warpM * 16 + (lane >> 2);
        const float* Arow = Eb + (size_t)(ch * 64) * 2048 + col0;
#pragma unroll
        for (int nt = 0; nt < 8; nt++) {
            const int col = warpN * 64 + nt * 8 + (lane & 3) * 2;
            float2 a0 = *reinterpret_cast<const float2*>(Arow + (size_t)r0 * 2048 + col);
            float2 a1 = *reinterpret_cast<const float2*>(Arow + (size_t)(r0 + 8) * 2048 + col);
            Rf[r0 * 132 + col]           = a0.x + acc[nt][0];
            Rf[r0 * 132 + col + 1]       = a0.y + acc[nt][1];
            Rf[(r0 + 8) * 132 + col]     = a1.x + acc[nt][2];
            Rf[(r0 + 8) * 132 + col + 1] = a1.y + acc[nt][3];
        }
    }
    __syncthreads();

    const int ty = tid >> 4, tx = tid & 15;
    float e[4][8];
#pragma unroll
    for (int rr = 0; rr < 4; rr++)
#pragma unroll
        for (int cc = 0; cc < 8; cc++) e[rr][cc] = 0.0f;
    for (int qq = 0; qq < 64; qq++) {
        float mv[4];
#pragma unroll
        for (int rr = 0; rr < 4; rr++) mv[rr] = Ms[(ty * 4 + rr) * 65 + qq];
        float4 rv0 = *reinterpret_cast<const float4*>(&Rf[qq * 132 + tx * 8]);
        float4 rv1 = *reinterpret_cast<const float4*>(&Rf[qq * 132 + tx * 8 + 4]);
#pragma unroll
        for (int rr = 0; rr < 4; rr++) {
            e[rr][0] += mv[rr] * rv0.x; e[rr][1] += mv[rr] * rv0.y;
            e[rr][2] += mv[rr] * rv0.z; e[rr][3] += mv[rr] * rv0.w;
            e[rr][4] += mv[rr] * rv1.x; e[rr][5] += mv[rr] * rv1.y;
            e[rr][6] += mv[rr] * rv1.z; e[rr][7] += mv[rr] * rv1.w;
        }
    }
#pragma unroll
    for (int rr = 0; rr < 4; rr++) {
        const int row = ch * 64 + ty * 4 + rr;
        *reinterpret_cast<float4*>(Eb + (size_t)row * 2048 + col0 + tx * 8) =
            make_float4(e[rr][0], e[rr][1], e[rr][2], e[rr][3]);
        *reinterpret_cast<float4*>(Eb + (size_t)row * 2048 + col0 + tx * 8 + 4) =
            make_float4(e[rr][4], e[rr][5], e[rr][6], e[rr][7]);
    }
#pragma unroll
    for (int cc = 0; cc < 8; cc++) {
        const int gcol = col0 + tx * 8 + cc;
        __half2 p0 = __halves2half2(__float2half_rn(e[0][cc]), __float2half_rn(e[1][cc]));
        __half2 p1 = __halves2half2(__float2half_rn(e[2][cc]), __float2half_rn(e[3][cc]));
        *reinterpret_cast<__half2*>(EhT + (size_t)gcol * 512 + ch * 64 + ty * 4)     = p0;
        *reinterpret_cast<__half2*>(EhT + (size_t)gcol * 512 + ch * 64 + ty * 4 + 2) = p1;
    }
}

// ================= fused sigmoid-gate + LayerNorm =================
__global__ __launch_bounds__(256) void gate_ln_kernel(
    const float* __restrict__ Z, const float* __restrict__ T, const float* __restrict__ X,
    const float* __restrict__ gamma, const float* __restrict__ beta, float* __restrict__ out)
{
    __shared__ float red[16];
    __shared__ float mu_s, rinv_s;
    const int n = blockIdx.x, tid = threadIdx.x;
    const size_t base = (size_t)n * H_ + tid * 4;
    float4 z = *(const float4*)(Z + base);
    float4 t = *(const float4*)(T + base);
    float4 x = *(const float4*)(X + base);
    float h[4];
    {
        float g;
        g = 1.0f / (1.0f + expf(-z.x)); h[0] = g * t.x + (1.0f - g) * x.x;
        g = 1.0f / (1.0f + expf(-z.y)); h[1] = g * t.y + (1.0f - g) * x.y;
        g = 1.0f / (1.0f + expf(-z.z)); h[2] = g * t.z + (1.0f - g) * x.z;
        g = 1.0f / (1.0f + expf(-z.w)); h[3] = g * t.w + (1.0f - g) * x.w;
    }
    float s = h[0] + h[1] + h[2] + h[3];
    float q = h[0]*h[0] + h[1]*h[1] + h[2]*h[2] + h[3]*h[3];
#pragma unroll
    for (int o = 16; o > 0; o >>= 1) {
        s += __shfl_xor_sync(0xffffffffu, s, o);
        q += __shfl_xor_sync(0xffffffffu, q, o);
    }
    const int lane = tid & 31, wid = tid >> 5;
    if (lane == 0) { red[wid] = s; red[8 + wid] = q; }
    __syncthreads();
    if (tid == 0) {
        float Sa = 0.0f, Q = 0.0f;
#pragma unroll
        for (int w = 0; w < 8; w++) { Sa += red[w]; Q += red[8 + w]; }
        float mu = Sa * (1.0f / H_);
        mu_s = mu; rinv_s = rsqrtf(Q * (1.0f / H_) - mu * mu + EPS_);
    }
    __syncthreads();
    const float mu = mu_s, rinv = rinv_s;
    float4 gm = *(const float4*)(gamma + tid * 4);
    float4 bt = *(const float4*)(beta + tid * 4);
    float4 o;
    o.x = (h[0] - mu) * rinv * gm.x + bt.x;
    o.y = (h[1] - mu) * rinv * gm.y + bt.y;
    o.z = (h[2] - mu) * rinv * gm.z + bt.z;
    o.w = (h[3] - mu) * rinv * gm.w + bt.w;
    *(float4*)(out + base) = o;
}

// ================= launch =================
extern "C" void kernel_launch(void* const* d_in, const int* in_sizes, int n_in,
                              void* d_out, int out_size)
{
    const float* x      = (const float*)d_in[0];
    const float* W_init = (const float*)d_in[1];
    const float* b_init = (const float*)d_in[2];
    const float* Wt     = (const float*)d_in[3];
    const float* bt     = (const float*)d_in[4];
    const float* Wo     = (const float*)d_in[5];
    const float* bo     = (const float*)d_in[6];
    const float* Wg     = (const float*)d_in[7];
    const float* bg     = (const float*)d_in[8];
    const float* gamma  = (const float*)d_in[9];
    const float* beta   = (const float*)d_in[10];
    float* out = (float*)d_out;

    float *pTE, *pTT, *pZ, *pC, *pbc;
    __half *pxh, *pSh, *pTTh, *pBh, *pBl, *pWoh, *pWol, *pWgh, *pWgl, *pCs;
    cudaGetSymbolAddress((void**)&pTE,  g_TE);
    cudaGetSymbolAddress((void**)&pTT,  g_ttt);
    cudaGetSymbolAddress((void**)&pZ,   g_Z);
    cudaGetSymbolAddress((void**)&pC,   g_C);
    cudaGetSymbolAddress((void**)&pCs,  g_Cs16);
    cudaGetSymbolAddress((void**)&pbc,  g_bcat);
    cudaGetSymbolAddress((void**)&pxh,  g_xh);
    cudaGetSymbolAddress((void**)&pSh,  g_Sh);
    cudaGetSymbolAddress((void**)&pTTh, g_TTh);
    cudaGetSymbolAddress((void**)&pBh,  g_Bh);
    cudaGetSymbolAddress((void**)&pBl,  g_Bl);
    cudaGetSymbolAddress((void**)&pWoh, g_Woh);
    cudaGetSymbolAddress((void**)&pWol, g_Wol);
    cudaGetSymbolAddress((void**)&pWgh, g_Wgh);
    cudaGetSymbolAddress((void**)&pWgl, g_Wgl);

    const int SMB = 2 * 12288 * 2;    // 49152 B: 2 stages x (Ah,Bh,Bl)
    const int SMG = 2 * 8192 * 2;     // 32768 B: gram
    const int SMS = 24576 + 64 * 132 * 4 + 64 * 65 * 4;
    cudaFuncSetAttribute(gemm_mma<0,0>, cudaFuncAttributeMaxDynamicSharedMemorySize, SMB);
    cudaFuncSetAttribute(gemm_mma<0,1>, cudaFuncAttributeMaxDynamicSharedMemorySize, SMB);
    cudaFuncSetAttribute(gemm_mma<1,0>, cudaFuncAttributeMaxDynamicSharedMemorySize, SMB);
    cudaFuncSetAttribute(gemm_mma<2,2>, cudaFuncAttributeMaxDynamicSharedMemorySize, SMG);
    cudaFuncSetAttribute(solve_mma_kernel, cudaFuncAttributeMaxDynamicSharedMemorySize, SMS);

    dim3 tb(32, 8);
    conv_x_kernel<<<N_ * H_ / 1024, 256>>>(x, pxh);
    tsplit_kernel<<<dim3(32, 32), tb>>>(Wt, nullptr, pBh, pBl, 1024, 1024, 0);
    tsplit_kernel<<<dim3(32, 32), tb>>>(W_init, Wt, pBh, pBl, 1024, 1024, 1024);
    tsplit_kernel<<<dim3(32, 32), tb>>>(Wo, nullptr, pWoh, pWol, 1024, 1024, 0);
    tsplit_kernel<<<dim3(64, 32), tb>>>(Wg, nullptr, pWgh, pWgl, 1024, 2048, 0);
    bcat_kernel<<<8, 256>>>(bt, b_init, pbc);

    // [T | A] = x @ [Wt | Winit-Wt] + [bt | binit-bt]  (N=2048)
    gemm_mma<0,0><<<dim3(16, 256), 256, SMB>>>(pxh, nullptr, pBh, pBl, pbc,
                                               pTE, nullptr, 1024, 2048);
    // Gram lower tiles: fp32 C(+1) and fp16(-SC*C)
    gemm_mma<2,2><<<dim3(10, 64), 256, SMG>>>(pxh, nullptr, nullptr, nullptr, nullptr,
                                              pC, pCs, 1024, 0);
    tri_inv_kernel<<<512, 64>>>();
    for (int ch = 0; ch < 8; ch++)
        solve_mma_kernel<<<dim3(8, 64), 256, SMS>>>(ch);
    // S = silu(T + E) -> fp16 (overwrites EhT region)
    silu_h_kernel<<<N_ * H_ / 1024, 256>>>(pSh);
    // ttt = S @ Wo + bo (EPI writes fp16 copy)
    gemm_mma<0,1><<<dim3(8, 256), 256, SMB>>>(pSh, nullptr, pWoh, pWol, bo,
                                              pTT, pTTh, 1024, 1024);
    // Z = [x, ttt] @ Wg + bg
    gemm_mma<1,0><<<dim3(8, 256), 256, SMB>>>(pxh, pTTh, pWgh, pWgl, bg,
                                              pZ, nullptr, 2048, 1024);
    // out = LN(sigmoid(Z)*ttt + (1-sigmoid(Z))*x)
    gate_ln_kernel<<<N_, 256>>>(pZ, pTT, x, gamma, beta, out);
}

// round 12
// speedup vs baseline: 5.5152x; 1.4381x over previous
#include <cuda_runtime.h>
#include <cuda_fp16.h>
#include <cstdint>
#include <math.h>

#define B_ 64
#define S_ 512
#define H_ 1024
#define I_ 1024
#define N_ (B_*S_)
#define SC (0.01f/1024.0f)
#define EPS_ 1e-5f

// ================= scratch =================
__device__ float  g_TE[(size_t)N_*2048];      // [T | A->E], ld=2048 (fp32)
__device__ float  g_ttt[(size_t)N_*H_];
__device__ float  g_Z[(size_t)N_*H_];
__device__ float  g_C[(size_t)B_*S_*S_];      // fp32 gram (+1)
__device__ __half g_Cs16[(size_t)B_*S_*S_];   // fp16(-SC * C)
__device__ float  g_Minv[(size_t)B_*8*64*64];
__device__ float  g_bcat[2048];
__device__ __half g_xh[(size_t)N_*H_];
__device__ __half g_Sh[(size_t)N_*I_];        // EhT during solve, then silu hi
__device__ __half g_TTh[(size_t)N_*H_];
__device__ __half g_Bh[(size_t)2048*1024];    // [Wt | Winit-Wt]^T  [n=2048][k=1024]
__device__ __half g_Woh[(size_t)1024*1024];   // Wo^T
__device__ __half g_Wgh[(size_t)1024*2048];   // Wg^T [n=1024][k=2048]

__constant__ int c_TI[10] = {0,1,1,2,2,2,3,3,3,3};
__constant__ int c_TJ[10] = {0,0,1,0,1,2,0,1,2,3};

// ================= helpers =================
__device__ __forceinline__ uint32_t smem_u32(const void* p) {
    uint32_t a;
    asm("{ .reg .u64 t; cvta.to.shared.u64 t, %1; cvt.u32.u64 %0, t; }" : "=r"(a) : "l"(p));
    return a;
}
__device__ __forceinline__ float silu_f(float v) { return v / (1.0f + expf(-v)); }

__device__ __forceinline__ void ldm_x4(uint32_t* r, uint32_t addr) {
    asm volatile("ldmatrix.sync.aligned.m8n8.x4.shared.b16 {%0,%1,%2,%3}, [%4];"
        : "=r"(r[0]), "=r"(r[1]), "=r"(r[2]), "=r"(r[3]) : "r"(addr));
}
__device__ __forceinline__ void mma16816(float* d, const uint32_t* a, uint32_t b0, uint32_t b1) {
    asm volatile("mma.sync.aligned.m16n8k16.row.col.f32.f16.f16.f32 "
        "{%0,%1,%2,%3},{%4,%5,%6,%7},{%8,%9},{%0,%1,%2,%3};"
        : "+f"(d[0]), "+f"(d[1]), "+f"(d[2]), "+f"(d[3])
        : "r"(a[0]), "r"(a[1]), "r"(a[2]), "r"(a[3]), "r"(b0), "r"(b1));
}

// cp.async ROWS x 32-half tile (64B/row), XOR-swizzled 16B chunks; g pre-offset to (row0,k)
template<int ROWS>
__device__ __forceinline__ void cp_rows(__half* s, const __half* __restrict__ g,
                                        int ld, int tid) {
#pragma unroll
    for (int i = 0; i < ROWS / 64; i++) {
        int cid = tid + 256 * i;
        int row = cid >> 2, c = cid & 3;
        const __half* gp = g + (size_t)row * ld + c * 8;
        int sc = c ^ ((row >> 1) & 3);
        uint32_t d = smem_u32(s + row * 32 + sc * 8);
        asm volatile("cp.async.cg.shared.global [%0], [%1], 16;" :: "r"(d), "l"(gp));
    }
}

// ============ 1-term fp16 mma.sync GEMM: C = A@B^T + bias ============
// MODE 0: A = Ah0 [M,1024]
// MODE 1: A = concat(Ah0, Ah1) along K (K=2048)
// MODE 2: gram: per-batch lower tiles of x x^T + 1
// EPI 1: also write fp16(C) to Ch;  EPI 2 (gram): fp32 C(+1) and Ch=fp16(-SC*C)
template<int MODE, int EPI>
__global__ __launch_bounds__(256, 2)
void gemm_mma(const __half* __restrict__ Ah0, const __half* __restrict__ Ah1,
              const __half* __restrict__ Bh, const float* __restrict__ bias,
              float* __restrict__ C, __half* __restrict__ Ch,
              int ldb, int ldc)
{
    extern __shared__ __align__(16) __half smem[];
    constexpr int SSTRIDE = 8192;   // halves per stage: A(4096) + B(4096)

    const int tid = threadIdx.x;
    const int warp = tid >> 5, lane = tid & 31;
    const int warpM = warp & 3, warpN = warp >> 2;   // 4 x 2 warps (32x64 each)
    const int K = (MODE == 1) ? 2048 : 1024;
    const int NS = K >> 5;

    size_t arow, brow; int crow0, ccol0, ldcc; float* cb;
    if (MODE == 2) {
        const int b = blockIdx.y;
        crow0 = c_TI[blockIdx.x] << 7; ccol0 = c_TJ[blockIdx.x] << 7;
        arow = (size_t)b * S_ + crow0; brow = (size_t)b * S_ + ccol0;
        cb = C + (size_t)b * S_ * S_; ldcc = S_;
        Ch = Ch + (size_t)b * S_ * S_;
    } else {
        arow = (size_t)blockIdx.y << 7; brow = (size_t)blockIdx.x << 7;
        crow0 = (int)arow; ccol0 = (int)brow; cb = C; ldcc = ldc;
    }

#define LOAD_STAGE(s_) do { \
        const int s__ = (s_); const int k0_ = s__ << 5; \
        __half* st_ = smem + (s__ % 3) * SSTRIDE; \
        if (MODE == 2) { \
            cp_rows<128>(st_,        Ah0 + arow * 1024 + k0_, 1024, tid); \
            cp_rows<128>(st_ + 4096, Ah0 + brow * 1024 + k0_, 1024, tid); \
        } else { \
            const __half* ah_ = Ah0; int ak_ = k0_; \
            if (MODE == 1 && k0_ >= 1024) { ah_ = Ah1; ak_ = k0_ - 1024; } \
            cp_rows<128>(st_,        ah_ + arow * 1024 + ak_, 1024, tid); \
            cp_rows<128>(st_ + 4096, Bh + brow * (size_t)ldb + k0_, ldb, tid); \
        } \
        asm volatile("cp.async.commit_group;" ::: "memory"); \
    } while (0)

    float acc[2][8][4];
#pragma unroll
    for (int mt = 0; mt < 2; mt++)
#pragma unroll
        for (int j = 0; j < 8; j++)
#pragma unroll
            for (int q = 0; q < 4; q++) acc[mt][j][q] = 0.0f;

    LOAD_STAGE(0);
    LOAD_STAGE(1);

    for (int s = 0; s < NS; s++) {
        if (s + 1 < NS) asm volatile("cp.async.wait_group 1;" ::: "memory");
        else            asm volatile("cp.async.wait_group 0;" ::: "memory");
        __syncthreads();
        const __half* st = smem + (s % 3) * SSTRIDE;
        const __half* Ahs = st;
        const __half* Bhs = st + 4096;
#pragma unroll
        for (int kk = 0; kk < 2; kk++) {
            const int q = lane >> 3, r = lane & 7;
            uint32_t af[2][4];
#pragma unroll
            for (int mt = 0; mt < 2; mt++) {
                const int row = warpM * 32 + mt * 16 + ((q & 1) ? 8 : 0) + r;
                const int c = kk * 2 + (q >> 1);
                ldm_x4(af[mt], smem_u32(Ahs + row * 32 + (c ^ ((row >> 1) & 3)) * 8));
            }
            uint32_t bf[4][4];
#pragma unroll
            for (int nt = 0; nt < 4; nt++) {
                const int row = warpN * 64 + nt * 16 + ((q >> 1) ? 8 : 0) + r;
                const int c = kk * 2 + (q & 1);
                ldm_x4(bf[nt], smem_u32(Bhs + row * 32 + (c ^ ((row >> 1) & 3)) * 8));
            }
#pragma unroll
            for (int mt = 0; mt < 2; mt++)
#pragma unroll
                for (int nt = 0; nt < 4; nt++) {
                    mma16816(acc[mt][nt * 2 + 0], af[mt], bf[nt][0], bf[nt][1]);
                    mma16816(acc[mt][nt * 2 + 1], af[mt], bf[nt][2], bf[nt][3]);
                }
        }
        if (s + 2 < NS) LOAD_STAGE(s + 2);
    }
#undef LOAD_STAGE

    // epilogue
    const int baseRow = crow0 + warpM * 32;
    const int baseCol = ccol0 + warpN * 64;
#pragma unroll
    for (int mt = 0; mt < 2; mt++) {
#pragma unroll
        for (int j = 0; j < 8; j++) {
            const int col = baseCol + j * 8 + (lane & 3) * 2;
            const int r0 = baseRow + mt * 16 + (lane >> 2);
            float bx, by;
            if (MODE == 2) { bx = 1.0f; by = 1.0f; }
            else { bx = bias[col]; by = bias[col + 1]; }
            float v0 = acc[mt][j][0] + bx, v1 = acc[mt][j][1] + by;
            float v2 = acc[mt][j][2] + bx, v3 = acc[mt][j][3] + by;
            *reinterpret_cast<float2*>(cb + (size_t)r0 * ldcc + col) = make_float2(v0, v1);
            *reinterpret_cast<float2*>(cb + (size_t)(r0 + 8) * ldcc + col) = make_float2(v2, v3);
            if (EPI == 1) {
                *reinterpret_cast<__half2*>(Ch + (size_t)r0 * ldcc + col) =
                    __halves2half2(__float2half_rn(v0), __float2half_rn(v1));
                *reinterpret_cast<__half2*>(Ch + (size_t)(r0 + 8) * ldcc + col) =
                    __halves2half2(__float2half_rn(v2), __float2half_rn(v3));
            }
            if (EPI == 2) {   // Cs16 = fp16(-SC * C)
                *reinterpret_cast<__half2*>(Ch + (size_t)r0 * ldcc + col) =
                    __halves2half2(__float2half_rn(-SC * v0), __float2half_rn(-SC * v1));
                *reinterpret_cast<__half2*>(Ch + (size_t)(r0 + 8) * ldcc + col) =
                    __halves2half2(__float2half_rn(-SC * v2), __float2half_rn(-SC * v3));
            }
        }
    }
}

// ================= prep kernels =================
__global__ void conv_x_kernel(const float* __restrict__ x, __half* __restrict__ xh) {
    size_t i = ((size_t)blockIdx.x * 256 + threadIdx.x) * 4;
    float4 v = *reinterpret_cast<const float4*>(x + i);
    *reinterpret_cast<__half2*>(xh + i) =
        __halves2half2(__float2half_rn(v.x), __float2half_rn(v.y));
    *reinterpret_cast<__half2*>(xh + i + 2) =
        __halves2half2(__float2half_rn(v.z), __float2half_rn(v.w));
}

// oh[(n+roff)*ldo + k] = fp16(W[k][n] - Wsub?[k][n]);  W is [K, N] row-major
__global__ void ttrans_kernel(const float* __restrict__ W, const float* __restrict__ Wsub,
                              __half* __restrict__ oh, int N, int ldo, int roff)
{
    __shared__ float t[32][33];
    const int k0 = blockIdx.x * 32, n0 = blockIdx.y * 32;
    const int tx = threadIdx.x, ty = threadIdx.y;
#pragma unroll
    for (int i = 0; i < 32; i += 8) {
        float v = W[(size_t)(k0 + ty + i) * N + n0 + tx];
        if (Wsub) v -= Wsub[(size_t)(k0 + ty + i) * N + n0 + tx];
        t[ty + i][tx] = v;
    }
    __syncthreads();
#pragma unroll
    for (int i = 0; i < 32; i += 8)
        oh[(size_t)(n0 + ty + i + roff) * ldo + k0 + tx] = __float2half_rn(t[tx][ty + i]);
}

__global__ void bcat_kernel(const float* __restrict__ bt, const float* __restrict__ bi,
                            float* __restrict__ bc) {
    int j = blockIdx.x * 256 + threadIdx.x;
    if (j < 1024) bc[j] = bt[j];
    else if (j < 2048) bc[j] = bi[j - 1024] - bt[j - 1024];
}

// S = silu(T + E) from g_TE (ld 2048) -> fp16 (ld 1024)
__global__ void silu_h_kernel(__half* __restrict__ Sh) {
    size_t idx4 = (size_t)blockIdx.x * 256 + threadIdx.x;
    size_t r = idx4 >> 8, j4 = (idx4 & 255) * 4;
    size_t base = r * 2048 + j4;
    float4 t = *reinterpret_cast<const float4*>(g_TE + base);
    float4 e = *reinterpret_cast<const float4*>(g_TE + base + 1024);
    float s0 = silu_f(t.x + e.x), s1 = silu_f(t.y + e.y);
    float s2 = silu_f(t.z + e.z), s3 = silu_f(t.w + e.w);
    size_t ob = r * 1024 + j4;
    *reinterpret_cast<__half2*>(Sh + ob) =
        __halves2half2(__float2half_rn(s0), __float2half_rn(s1));
    *reinterpret_cast<__half2*>(Sh + ob + 2) =
        __halves2half2(__float2half_rn(s2), __float2half_rn(s3));
}

// ================= triangular inverse per (batch, chunk) =================
__global__ __launch_bounds__(64) void tri_inv_kernel()
{
    __shared__ float L[64][65];
    __shared__ float Msm[64][65];
    const int bc = blockIdx.x, b = bc >> 3, ch = bc & 7;
    const int j = threadIdx.x;
    const float* Cb = g_C + (size_t)b * S_ * S_ + (size_t)(ch * 64) * S_ + ch * 64;
    for (int r = 0; r < 64; r++) L[r][j] = Cb[(size_t)r * S_ + j];
    for (int t = 0; t < 64; t++) Msm[t][j] = (t == j) ? 1.0f : 0.0f;
    __syncthreads();
    for (int t = 1; t < 64; t++) {
        if (t > j) {
            float a = 0.0f;
            for (int s = j; s < t; s++) a += L[t][s] * Msm[s][j];
            Msm[t][j] = -SC * a;
        }
    }
    float* Mo = g_Minv + (size_t)bc * 64 * 64;
    for (int r = 0; r < 64; r++) Mo[r * 64 + j] = Msm[r][j];
}

// ================= mma-based chunk solve =================
__global__ __launch_bounds__(256) void solve_mma_kernel(int ch)
{
    extern __shared__ __align__(16) char sm[];
    __half* As0 = (__half*)sm;            // 64x32
    __half* As1 = As0 + 2048;
    __half* Bs0 = As1 + 2048;             // 128x32
    __half* Bs1 = Bs0 + 4096;
    float*  Rf  = (float*)(Bs1 + 4096);   // [64][132]
    float*  Ms  = Rf + 64 * 132;          // [64][65]

    const int tid = threadIdx.x;
    const int warp = tid >> 5, lane = tid & 31;
    const int warpM = warp & 3, warpN = warp >> 2;
    const int b = blockIdx.y;
    const int col0 = blockIdx.x << 7;
    float* Eb = g_TE + (size_t)b * S_ * 2048 + 1024;
    const __half* Cs = g_Cs16 + (size_t)b * S_ * S_ + (size_t)(ch * 64) * S_;
    __half* EhT = g_Sh + (size_t)b * 1024 * 512;

    float acc[8][4];
#pragma unroll
    for (int nt = 0; nt < 8; nt++)
#pragma unroll
        for (int q = 0; q < 4; q++) acc[nt][q] = 0.0f;

    for (int pc = 0; pc < ch; pc++) {
        cp_rows<64>(As0, Cs + pc * 64, S_, tid);
        cp_rows<64>(As1, Cs + pc * 64 + 32, S_, tid);
        cp_rows<128>(Bs0, EhT + (size_t)col0 * 512 + pc * 64, 512, tid);
        cp_rows<128>(Bs1, EhT + (size_t)col0 * 512 + pc * 64 + 32, 512, tid);
        asm volatile("cp.async.commit_group;" ::: "memory");
        asm volatile("cp.async.wait_group 0;" ::: "memory");
        __syncthreads();
#pragma unroll
        for (int kk = 0; kk < 4; kk++) {
            const __half* As = (kk < 2) ? As0 : As1;
            const __half* Bs = (kk < 2) ? Bs0 : Bs1;
            const int kl = kk & 1;
            const int q = lane >> 3, r = lane & 7;
            uint32_t af[4];
            {
                const int row = warpM * 16 + ((q & 1) ? 8 : 0) + r;
                const int c = kl * 2 + (q >> 1);
                ldm_x4(af, smem_u32(As + row * 32 + (c ^ ((row >> 1) & 3)) * 8));
            }
            uint32_t bf[4][4];
#pragma unroll
            for (int ntc = 0; ntc < 4; ntc++) {
                const int row = warpN * 64 + ntc * 16 + ((q >> 1) ? 8 : 0) + r;
                const int c = kl * 2 + (q & 1);
                ldm_x4(bf[ntc], smem_u32(Bs + row * 32 + (c ^ ((row >> 1) & 3)) * 8));
            }
#pragma unroll
            for (int ntc = 0; ntc < 4; ntc++) {
                mma16816(acc[ntc * 2 + 0], af, bf[ntc][0], bf[ntc][1]);
                mma16816(acc[ntc * 2 + 1], af, bf[ntc][2], bf[ntc][3]);
            }
        }
        __syncthreads();
    }

    const float* Mo = g_Minv + (size_t)(b * 8 + ch) * 4096;
    for (int idx = tid; idx < 4096; idx += 256)
        Ms[(idx >> 6) * 65 + (idx & 63)] = Mo[idx];

    {
        const int r0 = warpM * 16 + (lane >> 2);
        const float* Arow = Eb + (size_t)(ch * 64) * 2048 + col0;
#pragma unroll
        for (int nt = 0; nt < 8; nt++) {
            const int col = warpN * 64 + nt * 8 + (lane & 3) * 2;
            float2 a0 = *reinterpret_cast<const float2*>(Arow + (size_t)r0 * 2048 + col);
            float2 a1 = *reinterpret_cast<const float2*>(Arow + (size_t)(r0 + 8) * 2048 + col);
            Rf[r0 * 132 + col]           = a0.x + acc[nt][0];
            Rf[r0 * 132 + col + 1]       = a0.y + acc[nt][1];
            Rf[(r0 + 8) * 132 + col]     = a1.x + acc[nt][2];
            Rf[(r0 + 8) * 132 + col + 1] = a1.y + acc[nt][3];
        }
    }
    __syncthreads();

    const int ty = tid >> 4, tx = tid & 15;
    float e[4][8];
#pragma unroll
    for (int rr = 0; rr < 4; rr++)
#pragma unroll
        for (int cc = 0; cc < 8; cc++) e[rr][cc] = 0.0f;
    for (int qq = 0; qq < 64; qq++) {
        float mv[4];
#pragma unroll
        for (int rr = 0; rr < 4; rr++) mv[rr] = Ms[(ty * 4 + rr) * 65 + qq];
        float4 rv0 = *reinterpret_cast<const float4*>(&Rf[qq * 132 + tx * 8]);
        float4 rv1 = *reinterpret_cast<const float4*>(&Rf[qq * 132 + tx * 8 + 4]);
#pragma unroll
        for (int rr = 0; rr < 4; rr++) {
            e[rr][0] += mv[rr] * rv0.x; e[rr][1] += mv[rr] * rv0.y;
            e[rr][2] += mv[rr] * rv0.z; e[rr][3] += mv[rr] * rv0.w;
            e[rr][4] += mv[rr] * rv1.x; e[rr][5] += mv[rr] * rv1.y;
            e[rr][6] += mv[rr] * rv1.z; e[rr][7] += mv[rr] * rv1.w;
        }
    }
#pragma unroll
    for (int rr = 0; rr < 4; rr++) {
        const int row = ch * 64 + ty * 4 + rr;
        *reinterpret_cast<float4*>(Eb + (size_t)row * 2048 + col0 + tx * 8) =
            make_float4(e[rr][0], e[rr][1], e[rr][2], e[rr][3]);
        *reinterpret_cast<float4*>(Eb + (size_t)row * 2048 + col0 + tx * 8 + 4) =
            make_float4(e[rr][4], e[rr][5], e[rr][6], e[rr][7]);
    }
#pragma unroll
    for (int cc = 0; cc < 8; cc++) {
        const int gcol = col0 + tx * 8 + cc;
        __half2 p0 = __halves2half2(__float2half_rn(e[0][cc]), __float2half_rn(e[1][cc]));
        __half2 p1 = __halves2half2(__float2half_rn(e[2][cc]), __float2half_rn(e[3][cc]));
        *reinterpret_cast<__half2*>(EhT + (size_t)gcol * 512 + ch * 64 + ty * 4)     = p0;
        *reinterpret_cast<__half2*>(EhT + (size_t)gcol * 512 + ch * 64 + ty * 4 + 2) = p1;
    }
}

// ================= fused sigmoid-gate + LayerNorm =================
__global__ __launch_bounds__(256) void gate_ln_kernel(
    const float* __restrict__ Z, const float* __restrict__ T, const float* __restrict__ X,
    const float* __restrict__ gamma, const float* __restrict__ beta, float* __restrict__ out)
{
    __shared__ float red[16];
    __shared__ float mu_s, rinv_s;
    const int n = blockIdx.x, tid = threadIdx.x;
    const size_t base = (size_t)n * H_ + tid * 4;
    float4 z = *(const float4*)(Z + base);
    float4 t = *(const float4*)(T + base);
    float4 x = *(const float4*)(X + base);
    float h[4];
    {
        float g;
        g = 1.0f / (1.0f + expf(-z.x)); h[0] = g * t.x + (1.0f - g) * x.x;
        g = 1.0f / (1.0f + expf(-z.y)); h[1] = g * t.y + (1.0f - g) * x.y;
        g = 1.0f / (1.0f + expf(-z.z)); h[2] = g * t.z + (1.0f - g) * x.z;
        g = 1.0f / (1.0f + expf(-z.w)); h[3] = g * t.w + (1.0f - g) * x.w;
    }
    float s = h[0] + h[1] + h[2] + h[3];
    float q = h[0]*h[0] + h[1]*h[1] + h[2]*h[2] + h[3]*h[3];
#pragma unroll
    for (int o = 16; o > 0; o >>= 1) {
        s += __shfl_xor_sync(0xffffffffu, s, o);
        q += __shfl_xor_sync(0xffffffffu, q, o);
    }
    const int lane = tid & 31, wid = tid >> 5;
    if (lane == 0) { red[wid] = s; red[8 + wid] = q; }
    __syncthreads();
    if (tid == 0) {
        float Sa = 0.0f, Q = 0.0f;
#pragma unroll
        for (int w = 0; w < 8; w++) { Sa += red[w]; Q += red[8 + w]; }
        float mu = Sa * (1.0f / H_);
        mu_s = mu; rinv_s = rsqrtf(Q * (1.0f / H_) - mu * mu + EPS_);
    }
    __syncthreads();
    const float mu = mu_s, rinv = rinv_s;
    float4 gm = *(const float4*)(gamma + tid * 4);
    float4 bt = *(const float4*)(beta + tid * 4);
    float4 o;
    o.x = (h[0] - mu) * rinv * gm.x + bt.x;
    o.y = (h[1] - mu) * rinv * gm.y + bt.y;
    o.z = (h[2] - mu) * rinv * gm.z + bt.z;
    o.w = (h[3] - mu) * rinv * gm.w + bt.w;
    *(float4*)(out + base) = o;
}

// ================= launch =================
extern "C" void kernel_launch(void* const* d_in, const int* in_sizes, int n_in,
                              void* d_out, int out_size)
{
    const float* x      = (const float*)d_in[0];
    const float* W_init = (const float*)d_in[1];
    const float* b_init = (const float*)d_in[2];
    const float* Wt     = (const float*)d_in[3];
    const float* bt     = (const float*)d_in[4];
    const float* Wo     = (const float*)d_in[5];
    const float* bo     = (const float*)d_in[6];
    const float* Wg     = (const float*)d_in[7];
    const float* bg     = (const float*)d_in[8];
    const float* gamma  = (const float*)d_in[9];
    const float* beta   = (const float*)d_in[10];
    float* out = (float*)d_out;

    float *pTE, *pTT, *pZ, *pC, *pbc;
    __half *pxh, *pSh, *pTTh, *pBh, *pWoh, *pWgh, *pCs;
    cudaGetSymbolAddress((void**)&pTE,  g_TE);
    cudaGetSymbolAddress((void**)&pTT,  g_ttt);
    cudaGetSymbolAddress((void**)&pZ,   g_Z);
    cudaGetSymbolAddress((void**)&pC,   g_C);
    cudaGetSymbolAddress((void**)&pCs,  g_Cs16);
    cudaGetSymbolAddress((void**)&pbc,  g_bcat);
    cudaGetSymbolAddress((void**)&pxh,  g_xh);
    cudaGetSymbolAddress((void**)&pSh,  g_Sh);
    cudaGetSymbolAddress((void**)&pTTh, g_TTh);
    cudaGetSymbolAddress((void**)&pBh,  g_Bh);
    cudaGetSymbolAddress((void**)&pWoh, g_Woh);
    cudaGetSymbolAddress((void**)&pWgh, g_Wgh);

    const int SMB = 3 * 8192 * 2;     // 49152 B: 3 stages x (A,B)
    const int SMS = 24576 + 64 * 132 * 4 + 64 * 65 * 4;
    cudaFuncSetAttribute(gemm_mma<0,0>, cudaFuncAttributeMaxDynamicSharedMemorySize, SMB);
    cudaFuncSetAttribute(gemm_mma<0,1>, cudaFuncAttributeMaxDynamicSharedMemorySize, SMB);
    cudaFuncSetAttribute(gemm_mma<1,0>, cudaFuncAttributeMaxDynamicSharedMemorySize, SMB);
    cudaFuncSetAttribute(gemm_mma<2,2>, cudaFuncAttributeMaxDynamicSharedMemorySize, SMB);
    cudaFuncSetAttribute(solve_mma_kernel, cudaFuncAttributeMaxDynamicSharedMemorySize, SMS);

    dim3 tb(32, 8);
    conv_x_kernel<<<N_ * H_ / 1024, 256>>>(x, pxh);
    ttrans_kernel<<<dim3(32, 32), tb>>>(Wt, nullptr, pBh, 1024, 1024, 0);
    ttrans_kernel<<<dim3(32, 32), tb>>>(W_init, Wt, pBh, 1024, 1024, 1024);
    ttrans_kernel<<<dim3(32, 32), tb>>>(Wo, nullptr, pWoh, 1024, 1024, 0);
    ttrans_kernel<<<dim3(64, 32), tb>>>(Wg, nullptr, pWgh, 1024, 2048, 0);
    bcat_kernel<<<8, 256>>>(bt, b_init, pbc);

    // [T | A] = x @ [Wt | Winit-Wt] + [bt | binit-bt]  (N=2048)
    gemm_mma<0,0><<<dim3(16, 256), 256, SMB>>>(pxh, nullptr, pBh, pbc,
                                               pTE, nullptr, 1024, 2048);
    // Gram lower tiles: fp32 C(+1) and fp16(-SC*C)
    gemm_mma<2,2><<<dim3(10, 64), 256, SMB>>>(pxh, nullptr, nullptr, nullptr,
                                              pC, pCs, 1024, 0);
    tri_inv_kernel<<<512, 64>>>();
    for (int ch = 0; ch < 8; ch++)
        solve_mma_kernel<<<dim3(8, 64), 256, SMS>>>(ch);
    // S = silu(T + E) -> fp16 (overwrites EhT region)
    silu_h_kernel<<<N_ * H_ / 1024, 256>>>(pSh);
    // ttt = S @ Wo + bo (EPI writes fp16 copy)
    gemm_mma<0,1><<<dim3(8, 256), 256, SMB>>>(pSh, nullptr, pWoh, bo,
                                              pTT, pTTh, 1024, 1024);
    // Z = [x, ttt] @ Wg + bg
    gemm_mma<1,0><<<dim3(8, 256), 256, SMB>>>(pxh, pTTh, pWgh, bg,
                                              pZ, nullptr, 2048, 1024);
    // out = LN(sigmoid(Z)*ttt + (1-sigmoid(Z))*x)
    gate_ln_kernel<<<N_, 256>>>(pZ, pTT, x, gamma, beta, out);
}

// round 13
// speedup vs baseline: 5.8173x; 1.0548x over previous
#include <cuda_runtime.h>
#include <cuda_fp16.h>
#include <cstdint>
#include <math.h>

#define B_ 64
#define S_ 512
#define H_ 1024
#define I_ 1024
#define N_ (B_*S_)
#define SC (0.01f/1024.0f)
#define EPS_ 1e-5f

// ================= scratch =================
__device__ float  g_TE[(size_t)N_*2048];      // [T | A], ld=2048 (fp32)
__device__ float  g_ttt[(size_t)N_*H_];
__device__ float  g_Z[(size_t)N_*H_];
__device__ __half g_Cs16[(size_t)B_*S_*S_];   // fp16(-SC * (gram+1))
__device__ float  g_Minv[(size_t)B_*8*64*64];
__device__ float  g_bcat[2048];
__device__ __half g_xh[(size_t)N_*H_];
__device__ __half g_Sh[(size_t)N_*I_];        // silu(T+E) fp16
__device__ __half g_EhT[(size_t)B_*1024*512]; // E transposed fp16 [b][col][row]
__device__ __half g_TTh[(size_t)N_*H_];
__device__ __half g_Bh[(size_t)2048*1024];    // [Wt | Winit-Wt]^T  [n=2048][k=1024]
__device__ __half g_Woh[(size_t)1024*1024];   // Wo^T
__device__ __half g_Wgh[(size_t)1024*2048];   // Wg^T [n=1024][k=2048]

__constant__ int c_TI[10] = {0,1,1,2,2,2,3,3,3,3};
__constant__ int c_TJ[10] = {0,0,1,0,1,2,0,1,2,3};

// ================= helpers =================
__device__ __forceinline__ uint32_t smem_u32(const void* p) {
    uint32_t a;
    asm("{ .reg .u64 t; cvta.to.shared.u64 t, %1; cvt.u32.u64 %0, t; }" : "=r"(a) : "l"(p));
    return a;
}
__device__ __forceinline__ float silu_f(float v) { return v / (1.0f + expf(-v)); }

__device__ __forceinline__ void ldm_x4(uint32_t* r, uint32_t addr) {
    asm volatile("ldmatrix.sync.aligned.m8n8.x4.shared.b16 {%0,%1,%2,%3}, [%4];"
        : "=r"(r[0]), "=r"(r[1]), "=r"(r[2]), "=r"(r[3]) : "r"(addr));
}
__device__ __forceinline__ void mma16816(float* d, const uint32_t* a, uint32_t b0, uint32_t b1) {
    asm volatile("mma.sync.aligned.m16n8k16.row.col.f32.f16.f16.f32 "
        "{%0,%1,%2,%3},{%4,%5,%6,%7},{%8,%9},{%0,%1,%2,%3};"
        : "+f"(d[0]), "+f"(d[1]), "+f"(d[2]), "+f"(d[3])
        : "r"(a[0]), "r"(a[1]), "r"(a[2]), "r"(a[3]), "r"(b0), "r"(b1));
}

// cp.async ROWS x 32-half tile (64B/row), XOR-swizzled 16B chunks; g pre-offset to (row0,k)
template<int ROWS>
__device__ __forceinline__ void cp_rows(__half* s, const __half* __restrict__ g,
                                        int ld, int tid) {
#pragma unroll
    for (int i = 0; i < ROWS / 64; i++) {
        int cid = tid + 256 * i;
        int row = cid >> 2, c = cid & 3;
        const __half* gp = g + (size_t)row * ld + c * 8;
        int sc = c ^ ((row >> 1) & 3);
        uint32_t d = smem_u32(s + row * 32 + sc * 8);
        asm volatile("cp.async.cg.shared.global [%0], [%1], 16;" :: "r"(d), "l"(gp));
    }
}

// ============ 1-term fp16 mma.sync GEMM: C = A@B^T + bias ============
// MODE 0: A = Ah0 [M,1024]
// MODE 1: A = concat(Ah0, Ah1) along K (K=2048)
// MODE 2: gram: per-batch lower tiles; EPI 2: write ONLY Ch = fp16(-SC*(xx^T+1))
// EPI 1: also write fp16(C) to Ch
template<int MODE, int EPI>
__global__ __launch_bounds__(256, 2)
void gemm_mma(const __half* __restrict__ Ah0, const __half* __restrict__ Ah1,
              const __half* __restrict__ Bh, const float* __restrict__ bias,
              float* __restrict__ C, __half* __restrict__ Ch,
              int ldb, int ldc)
{
    extern __shared__ __align__(16) __half smem[];
    constexpr int SSTRIDE = 8192;   // halves per stage: A(4096) + B(4096)

    const int tid = threadIdx.x;
    const int warp = tid >> 5, lane = tid & 31;
    const int warpM = warp & 3, warpN = warp >> 2;   // 4 x 2 warps (32x64 each)
    const int K = (MODE == 1) ? 2048 : 1024;
    const int NS = K >> 5;

    size_t arow, brow; int crow0, ccol0, ldcc; float* cb;
    if (MODE == 2) {
        const int b = blockIdx.y;
        crow0 = c_TI[blockIdx.x] << 7; ccol0 = c_TJ[blockIdx.x] << 7;
        arow = (size_t)b * S_ + crow0; brow = (size_t)b * S_ + ccol0;
        cb = C; ldcc = S_;
        Ch = Ch + (size_t)b * S_ * S_;
    } else {
        arow = (size_t)blockIdx.y << 7; brow = (size_t)blockIdx.x << 7;
        crow0 = (int)arow; ccol0 = (int)brow; cb = C; ldcc = ldc;
    }

#define LOAD_STAGE(s_) do { \
        const int s__ = (s_); const int k0_ = s__ << 5; \
        __half* st_ = smem + (s__ % 3) * SSTRIDE; \
        if (MODE == 2) { \
            cp_rows<128>(st_,        Ah0 + arow * 1024 + k0_, 1024, tid); \
            cp_rows<128>(st_ + 4096, Ah0 + brow * 1024 + k0_, 1024, tid); \
        } else { \
            const __half* ah_ = Ah0; int ak_ = k0_; \
            if (MODE == 1 && k0_ >= 1024) { ah_ = Ah1; ak_ = k0_ - 1024; } \
            cp_rows<128>(st_,        ah_ + arow * 1024 + ak_, 1024, tid); \
            cp_rows<128>(st_ + 4096, Bh + brow * (size_t)ldb + k0_, ldb, tid); \
        } \
        asm volatile("cp.async.commit_group;" ::: "memory"); \
    } while (0)

    float acc[2][8][4];
#pragma unroll
    for (int mt = 0; mt < 2; mt++)
#pragma unroll
        for (int j = 0; j < 8; j++)
#pragma unroll
            for (int q = 0; q < 4; q++) acc[mt][j][q] = 0.0f;

    LOAD_STAGE(0);
    LOAD_STAGE(1);

    for (int s = 0; s < NS; s++) {
        if (s + 1 < NS) asm volatile("cp.async.wait_group 1;" ::: "memory");
        else            asm volatile("cp.async.wait_group 0;" ::: "memory");
        __syncthreads();
        const __half* st = smem + (s % 3) * SSTRIDE;
        const __half* Ahs = st;
        const __half* Bhs = st + 4096;
#pragma unroll
        for (int kk = 0; kk < 2; kk++) {
            const int q = lane >> 3, r = lane & 7;
            uint32_t af[2][4];
#pragma unroll
            for (int mt = 0; mt < 2; mt++) {
                const int row = warpM * 32 + mt * 16 + ((q & 1) ? 8 : 0) + r;
                const int c = kk * 2 + (q >> 1);
                ldm_x4(af[mt], smem_u32(Ahs + row * 32 + (c ^ ((row >> 1) & 3)) * 8));
            }
            uint32_t bf[4][4];
#pragma unroll
            for (int nt = 0; nt < 4; nt++) {
                const int row = warpN * 64 + nt * 16 + ((q >> 1) ? 8 : 0) + r;
                const int c = kk * 2 + (q & 1);
                ldm_x4(bf[nt], smem_u32(Bhs + row * 32 + (c ^ ((row >> 1) & 3)) * 8));
            }
#pragma unroll
            for (int mt = 0; mt < 2; mt++)
#pragma unroll
                for (int nt = 0; nt < 4; nt++) {
                    mma16816(acc[mt][nt * 2 + 0], af[mt], bf[nt][0], bf[nt][1]);
                    mma16816(acc[mt][nt * 2 + 1], af[mt], bf[nt][2], bf[nt][3]);
                }
        }
        if (s + 2 < NS) LOAD_STAGE(s + 2);
    }
#undef LOAD_STAGE

    // epilogue
    const int baseRow = crow0 + warpM * 32;
    const int baseCol = ccol0 + warpN * 64;
#pragma unroll
    for (int mt = 0; mt < 2; mt++) {
#pragma unroll
        for (int j = 0; j < 8; j++) {
            const int col = baseCol + j * 8 + (lane & 3) * 2;
            const int r0 = baseRow + mt * 16 + (lane >> 2);
            float bx, by;
            if (MODE == 2) { bx = 1.0f; by = 1.0f; }
            else { bx = bias[col]; by = bias[col + 1]; }
            float v0 = acc[mt][j][0] + bx, v1 = acc[mt][j][1] + by;
            float v2 = acc[mt][j][2] + bx, v3 = acc[mt][j][3] + by;
            if (EPI != 2) {
                *reinterpret_cast<float2*>(cb + (size_t)r0 * ldcc + col) = make_float2(v0, v1);
                *reinterpret_cast<float2*>(cb + (size_t)(r0 + 8) * ldcc + col) = make_float2(v2, v3);
            }
            if (EPI == 1) {
                *reinterpret_cast<__half2*>(Ch + (size_t)r0 * ldcc + col) =
                    __halves2half2(__float2half_rn(v0), __float2half_rn(v1));
                *reinterpret_cast<__half2*>(Ch + (size_t)(r0 + 8) * ldcc + col) =
                    __halves2half2(__float2half_rn(v2), __float2half_rn(v3));
            }
            if (EPI == 2) {   // Cs16 = fp16(-SC * (gram+1))
                *reinterpret_cast<__half2*>(Ch + (size_t)r0 * ldcc + col) =
                    __halves2half2(__float2half_rn(-SC * v0), __float2half_rn(-SC * v1));
                *reinterpret_cast<__half2*>(Ch + (size_t)(r0 + 8) * ldcc + col) =
                    __halves2half2(__float2half_rn(-SC * v2), __float2half_rn(-SC * v3));
            }
        }
    }
}

// ================= prep kernels =================
__global__ void conv_x_kernel(const float* __restrict__ x, __half* __restrict__ xh) {
    size_t i = ((size_t)blockIdx.x * 256 + threadIdx.x) * 4;
    float4 v = *reinterpret_cast<const float4*>(x + i);
    *reinterpret_cast<__half2*>(xh + i) =
        __halves2half2(__float2half_rn(v.x), __float2half_rn(v.y));
    *reinterpret_cast<__half2*>(xh + i + 2) =
        __halves2half2(__float2half_rn(v.z), __float2half_rn(v.w));
}

// oh[(n+roff)*ldo + k] = fp16(W[k][n] - Wsub?[k][n]);  W is [K, N] row-major
__global__ void ttrans_kernel(const float* __restrict__ W, const float* __restrict__ Wsub,
                              __half* __restrict__ oh, int N, int ldo, int roff)
{
    __shared__ float t[32][33];
    const int k0 = blockIdx.x * 32, n0 = blockIdx.y * 32;
    const int tx = threadIdx.x, ty = threadIdx.y;
#pragma unroll
    for (int i = 0; i < 32; i += 8) {
        float v = W[(size_t)(k0 + ty + i) * N + n0 + tx];
        if (Wsub) v -= Wsub[(size_t)(k0 + ty + i) * N + n0 + tx];
        t[ty + i][tx] = v;
    }
    __syncthreads();
#pragma unroll
    for (int i = 0; i < 32; i += 8)
        oh[(size_t)(n0 + ty + i + roff) * ldo + k0 + tx] = __float2half_rn(t[tx][ty + i]);
}

__global__ void bcat_kernel(const float* __restrict__ bt, const float* __restrict__ bi,
                            float* __restrict__ bc) {
    int j = blockIdx.x * 256 + threadIdx.x;
    if (j < 1024) bc[j] = bt[j];
    else if (j < 2048) bc[j] = bi[j - 1024] - bt[j - 1024];
}

// ================= triangular inverse per (batch, chunk), from Cs16 =================
// Cs16 = -SC*(L+1-ish); recurrence: M[t][j] = sum_{s=j}^{t-1} Cs16[t][s] * M[s][j]
__global__ __launch_bounds__(64) void tri_inv_kernel()
{
    __shared__ float L[64][65];
    __shared__ float Msm[64][65];
    const int bc = blockIdx.x, b = bc >> 3, ch = bc & 7;
    const int j = threadIdx.x;
    const __half* Cb = g_Cs16 + (size_t)b * S_ * S_ + (size_t)(ch * 64) * S_ + ch * 64;
    for (int r = 0; r < 64; r++) L[r][j] = __half2float(Cb[(size_t)r * S_ + j]);
    for (int t = 0; t < 64; t++) Msm[t][j] = (t == j) ? 1.0f : 0.0f;
    __syncthreads();
    for (int t = 1; t < 64; t++) {
        if (t > j) {
            float a = 0.0f;
            for (int s = j; s < t; s++) a += L[t][s] * Msm[s][j];
            Msm[t][j] = a;
        }
    }
    float* Mo = g_Minv + (size_t)bc * 64 * 64;
    for (int r = 0; r < 64; r++) Mo[r * 64 + j] = Msm[r][j];
}

// ================= fused chunked solve + silu (single launch) =================
// grid (8 colblks, 64 batches). Each CTA owns E[:, col0:col0+128] for one batch
// and loops chunks ch=0..7 internally (no cross-CTA dependency).
__global__ __launch_bounds__(256) void solve_all_kernel()
{
    extern __shared__ __align__(16) char sm[];
    __half* As0 = (__half*)sm;            // 64x32
    __half* As1 = As0 + 2048;
    __half* Bs0 = As1 + 2048;             // 128x32
    __half* Bs1 = Bs0 + 4096;
    float*  Rf  = (float*)(Bs1 + 4096);   // [64][132]
    float*  Ms  = Rf + 64 * 132;          // [64][65]

    const int tid = threadIdx.x;
    const int warp = tid >> 5, lane = tid & 31;
    const int warpM = warp & 3, warpN = warp >> 2;
    const int b = blockIdx.y;
    const int col0 = blockIdx.x << 7;
    const float* TEb = g_TE + (size_t)b * S_ * 2048;          // T at +0, A at +1024
    const __half* CsB = g_Cs16 + (size_t)b * S_ * S_;
    __half* EhT = g_EhT + (size_t)b * 1024 * 512;
    __half* ShB = g_Sh + (size_t)b * S_ * 1024;

    for (int ch = 0; ch < 8; ch++) {
        const __half* Cs = CsB + (size_t)(ch * 64) * S_;

        float acc[8][4];
#pragma unroll
        for (int nt = 0; nt < 8; nt++)
#pragma unroll
            for (int q = 0; q < 4; q++) acc[nt][q] = 0.0f;

        for (int pc = 0; pc < ch; pc++) {
            cp_rows<64>(As0, Cs + pc * 64, S_, tid);
            cp_rows<64>(As1, Cs + pc * 64 + 32, S_, tid);
            cp_rows<128>(Bs0, EhT + (size_t)col0 * 512 + pc * 64, 512, tid);
            cp_rows<128>(Bs1, EhT + (size_t)col0 * 512 + pc * 64 + 32, 512, tid);
            asm volatile("cp.async.commit_group;" ::: "memory");
            asm volatile("cp.async.wait_group 0;" ::: "memory");
            __syncthreads();
#pragma unroll
            for (int kk = 0; kk < 4; kk++) {
                const __half* As = (kk < 2) ? As0 : As1;
                const __half* Bs = (kk < 2) ? Bs0 : Bs1;
                const int kl = kk & 1;
                const int q = lane >> 3, r = lane & 7;
                uint32_t af[4];
                {
                    const int row = warpM * 16 + ((q & 1) ? 8 : 0) + r;
                    const int c = kl * 2 + (q >> 1);
                    ldm_x4(af, smem_u32(As + row * 32 + (c ^ ((row >> 1) & 3)) * 8));
                }
                uint32_t bf[4][4];
#pragma unroll
                for (int ntc = 0; ntc < 4; ntc++) {
                    const int row = warpN * 64 + ntc * 16 + ((q >> 1) ? 8 : 0) + r;
                    const int c = kl * 2 + (q & 1);
                    ldm_x4(bf[ntc], smem_u32(Bs + row * 32 + (c ^ ((row >> 1) & 3)) * 8));
                }
#pragma unroll
                for (int ntc = 0; ntc < 4; ntc++) {
                    mma16816(acc[ntc * 2 + 0], af, bf[ntc][0], bf[ntc][1]);
                    mma16816(acc[ntc * 2 + 1], af, bf[ntc][2], bf[ntc][3]);
                }
            }
            __syncthreads();
        }

        // load Minv for (b, ch)
        const float* Mo = g_Minv + (size_t)(b * 8 + ch) * 4096;
        for (int idx = tid; idx < 4096; idx += 256)
            Ms[(idx >> 6) * 65 + (idx & 63)] = Mo[idx];

        // R = A + acc -> Rf
        {
            const int r0 = warpM * 16 + (lane >> 2);
            const float* Arow = TEb + (size_t)(ch * 64) * 2048 + 1024 + col0;
#pragma unroll
            for (int nt = 0; nt < 8; nt++) {
                const int col = warpN * 64 + nt * 8 + (lane & 3) * 2;
                float2 a0 = *reinterpret_cast<const float2*>(Arow + (size_t)r0 * 2048 + col);
                float2 a1 = *reinterpret_cast<const float2*>(Arow + (size_t)(r0 + 8) * 2048 + col);
                Rf[r0 * 132 + col]           = a0.x + acc[nt][0];
                Rf[r0 * 132 + col + 1]       = a0.y + acc[nt][1];
                Rf[(r0 + 8) * 132 + col]     = a1.x + acc[nt][2];
                Rf[(r0 + 8) * 132 + col + 1] = a1.y + acc[nt][3];
            }
        }
        __syncthreads();

        // E = Minv @ R (SIMT, K=64)
        const int ty = tid >> 4, tx = tid & 15;
        float e[4][8];
#pragma unroll
        for (int rr = 0; rr < 4; rr++)
#pragma unroll
            for (int cc = 0; cc < 8; cc++) e[rr][cc] = 0.0f;
        for (int qq = 0; qq < 64; qq++) {
            float mv[4];
#pragma unroll
            for (int rr = 0; rr < 4; rr++) mv[rr] = Ms[(ty * 4 + rr) * 65 + qq];
            float4 rv0 = *reinterpret_cast<const float4*>(&Rf[qq * 132 + tx * 8]);
            float4 rv1 = *reinterpret_cast<const float4*>(&Rf[qq * 132 + tx * 8 + 4]);
#pragma unroll
            for (int rr = 0; rr < 4; rr++) {
                e[rr][0] += mv[rr] * rv0.x; e[rr][1] += mv[rr] * rv0.y;
                e[rr][2] += mv[rr] * rv0.z; e[rr][3] += mv[rr] * rv0.w;
                e[rr][4] += mv[rr] * rv1.x; e[rr][5] += mv[rr] * rv1.y;
                e[rr][6] += mv[rr] * rv1.z; e[rr][7] += mv[rr] * rv1.w;
            }
        }

        // write EhT fp16 (for later chunks' corrections)
#pragma unroll
        for (int cc = 0; cc < 8; cc++) {
            const int gcol = col0 + tx * 8 + cc;
            __half2 p0 = __halves2half2(__float2half_rn(e[0][cc]), __float2half_rn(e[1][cc]));
            __half2 p1 = __halves2half2(__float2half_rn(e[2][cc]), __float2half_rn(e[3][cc]));
            *reinterpret_cast<__half2*>(EhT + (size_t)gcol * 512 + ch * 64 + ty * 4)     = p0;
            *reinterpret_cast<__half2*>(EhT + (size_t)gcol * 512 + ch * 64 + ty * 4 + 2) = p1;
        }
        // fused: S = silu(T + E) -> fp16 Sh
#pragma unroll
        for (int rr = 0; rr < 4; rr++) {
            const int row = ch * 64 + ty * 4 + rr;
            const float* Trow = TEb + (size_t)row * 2048 + col0 + tx * 8;
            float4 t0 = *reinterpret_cast<const float4*>(Trow);
            float4 t1 = *reinterpret_cast<const float4*>(Trow + 4);
            __half2 s0 = __halves2half2(__float2half_rn(silu_f(t0.x + e[rr][0])),
                                        __float2half_rn(silu_f(t0.y + e[rr][1])));
            __half2 s1 = __halves2half2(__float2half_rn(silu_f(t0.z + e[rr][2])),
                                        __float2half_rn(silu_f(t0.w + e[rr][3])));
            __half2 s2 = __halves2half2(__float2half_rn(silu_f(t1.x + e[rr][4])),
                                        __float2half_rn(silu_f(t1.y + e[rr][5])));
            __half2 s3 = __halves2half2(__float2half_rn(silu_f(t1.z + e[rr][6])),
                                        __float2half_rn(silu_f(t1.w + e[rr][7])));
            __half* Srow = ShB + (size_t)row * 1024 + col0 + tx * 8;
            *reinterpret_cast<__half2*>(Srow)     = s0;
            *reinterpret_cast<__half2*>(Srow + 2) = s1;
            *reinterpret_cast<__half2*>(Srow + 4) = s2;
            *reinterpret_cast<__half2*>(Srow + 6) = s3;
        }
        __syncthreads();   // EhT visible + smem reusable for next chunk
    }
}

// ================= fused sigmoid-gate + LayerNorm =================
__global__ __launch_bounds__(256) void gate_ln_kernel(
    const float* __restrict__ Z, const float* __restrict__ T, const float* __restrict__ X,
    const float* __restrict__ gamma, const float* __restrict__ beta, float* __restrict__ out)
{
    __shared__ float red[16];
    __shared__ float mu_s, rinv_s;
    const int n = blockIdx.x, tid = threadIdx.x;
    const size_t base = (size_t)n * H_ + tid * 4;
    float4 z = *(const float4*)(Z + base);
    float4 t = *(const float4*)(T + base);
    float4 x = *(const float4*)(X + base);
    float h[4];
    {
        float g;
        g = 1.0f / (1.0f + expf(-z.x)); h[0] = g * t.x + (1.0f - g) * x.x;
        g = 1.0f / (1.0f + expf(-z.y)); h[1] = g * t.y + (1.0f - g) * x.y;
        g = 1.0f / (1.0f + expf(-z.z)); h[2] = g * t.z + (1.0f - g) * x.z;
        g = 1.0f / (1.0f + expf(-z.w)); h[3] = g * t.w + (1.0f - g) * x.w;
    }
    float s = h[0] + h[1] + h[2] + h[3];
    float q = h[0]*h[0] + h[1]*h[1] + h[2]*h[2] + h[3]*h[3];
#pragma unroll
    for (int o = 16; o > 0; o >>= 1) {
        s += __shfl_xor_sync(0xffffffffu, s, o);
        q += __shfl_xor_sync(0xffffffffu, q, o);
    }
    const int lane = tid & 31, wid = tid >> 5;
    if (lane == 0) { red[wid] = s; red[8 + wid] = q; }
    __syncthreads();
    if (tid == 0) {
        float Sa = 0.0f, Q = 0.0f;
#pragma unroll
        for (int w = 0; w < 8; w++) { Sa += red[w]; Q += red[8 + w]; }
        float mu = Sa * (1.0f / H_);
        mu_s = mu; rinv_s = rsqrtf(Q * (1.0f / H_) - mu * mu + EPS_);
    }
    __syncthreads();
    const float mu = mu_s, rinv = rinv_s;
    float4 gm = *(const float4*)(gamma + tid * 4);
    float4 bt = *(const float4*)(beta + tid * 4);
    float4 o;
    o.x = (h[0] - mu) * rinv * gm.x + bt.x;
    o.y = (h[1] - mu) * rinv * gm.y + bt.y;
    o.z = (h[2] - mu) * rinv * gm.z + bt.z;
    o.w = (h[3] - mu) * rinv * gm.w + bt.w;
    *(float4*)(out + base) = o;
}

// ================= launch =================
extern "C" void kernel_launch(void* const* d_in, const int* in_sizes, int n_in,
                              void* d_out, int out_size)
{
    const float* x      = (const float*)d_in[0];
    const float* W_init = (const float*)d_in[1];
    const float* b_init = (const float*)d_in[2];
    const float* Wt     = (const float*)d_in[3];
    const float* bt     = (const float*)d_in[4];
    const float* Wo     = (const float*)d_in[5];
    const float* bo     = (const float*)d_in[6];
    const float* Wg     = (const float*)d_in[7];
    const float* bg     = (const float*)d_in[8];
    const float* gamma  = (const float*)d_in[9];
    const float* beta   = (const float*)d_in[10];
    float* out = (float*)d_out;

    float *pTE, *pTT, *pZ, *pbc;
    __half *pxh, *pSh, *pTTh, *pBh, *pWoh, *pWgh, *pCs;
    cudaGetSymbolAddress((void**)&pTE,  g_TE);
    cudaGetSymbolAddress((void**)&pTT,  g_ttt);
    cudaGetSymbolAddress((void**)&pZ,   g_Z);
    cudaGetSymbolAddress((void**)&pCs,  g_Cs16);
    cudaGetSymbolAddress((void**)&pbc,  g_bcat);
    cudaGetSymbolAddress((void**)&pxh,  g_xh);
    cudaGetSymbolAddress((void**)&pSh,  g_Sh);
    cudaGetSymbolAddress((void**)&pTTh, g_TTh);
    cudaGetSymbolAddress((void**)&pBh,  g_Bh);
    cudaGetSymbolAddress((void**)&pWoh, g_Woh);
    cudaGetSymbolAddress((void**)&pWgh, g_Wgh);

    const int SMB = 3 * 8192 * 2;     // 49152 B: 3 stages x (A,B)
    const int SMS = 24576 + 64 * 132 * 4 + 64 * 65 * 4;
    cudaFuncSetAttribute(gemm_mma<0,0>, cudaFuncAttributeMaxDynamicSharedMemorySize, SMB);
    cudaFuncSetAttribute(gemm_mma<0,1>, cudaFuncAttributeMaxDynamicSharedMemorySize, SMB);
    cudaFuncSetAttribute(gemm_mma<1,0>, cudaFuncAttributeMaxDynamicSharedMemorySize, SMB);
    cudaFuncSetAttribute(gemm_mma<2,2>, cudaFuncAttributeMaxDynamicSharedMemorySize, SMB);
    cudaFuncSetAttribute(solve_all_kernel, cudaFuncAttributeMaxDynamicSharedMemorySize, SMS);

    dim3 tb(32, 8);
    conv_x_kernel<<<N_ * H_ / 1024, 256>>>(x, pxh);
    ttrans_kernel<<<dim3(32, 32), tb>>>(Wt, nullptr, pBh, 1024, 1024, 0);
    ttrans_kernel<<<dim3(32, 32), tb>>>(W_init, Wt, pBh, 1024, 1024, 1024);
    ttrans_kernel<<<dim3(32, 32), tb>>>(Wo, nullptr, pWoh, 1024, 1024, 0);
    ttrans_kernel<<<dim3(64, 32), tb>>>(Wg, nullptr, pWgh, 1024, 2048, 0);
    bcat_kernel<<<8, 256>>>(bt, b_init, pbc);

    // [T | A] = x @ [Wt | Winit-Wt] + [bt | binit-bt]  (N=2048)
    gemm_mma<0,0><<<dim3(16, 256), 256, SMB>>>(pxh, nullptr, pBh, pbc,
                                               pTE, nullptr, 1024, 2048);
    // Gram lower tiles -> Cs16 = fp16(-SC*(xx^T+1)) only
    gemm_mma<2,2><<<dim3(10, 64), 256, SMB>>>(pxh, nullptr, nullptr, nullptr,
                                              nullptr, pCs, 1024, 0);
    tri_inv_kernel<<<512, 64>>>();
    // single fused solve (chunk loop inside) + silu -> Sh
    solve_all_kernel<<<dim3(8, 64), 256, SMS>>>();
    // ttt = S @ Wo + bo (EPI writes fp16 copy)
    gemm_mma<0,1><<<dim3(8, 256), 256, SMB>>>(pSh, nullptr, pWoh, bo,
                                              pTT, pTTh, 1024, 1024);
    // Z = [x, ttt] @ Wg + bg
    gemm_mma<1,0><<<dim3(8, 256), 256, SMB>>>(pxh, pTTh, pWgh, bg,
                                              pZ, nullptr, 2048, 1024);
    // out = LN(sigmoid(Z)*ttt + (1-sigmoid(Z))*x)
    gate_ln_kernel<<<N_, 256>>>(pZ, pTT, x, gamma, beta, out);
}

// round 14
// speedup vs baseline: 5.8215x; 1.0007x over previous
#include <cuda_runtime.h>
#include <cuda_fp16.h>
#include <cstdint>
#include <math.h>

#define B_ 64
#define S_ 512
#define H_ 1024
#define I_ 1024
#define N_ (B_*S_)
#define SC (0.01f/1024.0f)
#define EPS_ 1e-5f

// ================= scratch =================
__device__ float  g_TE[(size_t)N_*2048];      // [T | A], ld=2048 (fp32)
__device__ float  g_ttt[(size_t)N_*H_];
__device__ float  g_Z[(size_t)N_*H_];
__device__ __half g_Cs16[(size_t)B_*S_*S_];   // fp16(-SC * (gram+1))
__device__ float  g_Minv[(size_t)B_*8*64*64];
__device__ float  g_bcat[2048];
__device__ __half g_xh[(size_t)N_*H_];
__device__ __half g_Sh[(size_t)N_*I_];        // silu(T+E) fp16
__device__ __half g_EhT[(size_t)B_*1024*512]; // E transposed fp16 [b][col][row]
__device__ __half g_TTh[(size_t)N_*H_];
__device__ __half g_Bh[(size_t)2048*1024];    // [Wt | Winit-Wt]^T  [n=2048][k=1024]
__device__ __half g_Woh[(size_t)1024*1024];   // Wo^T
__device__ __half g_Wgh[(size_t)1024*2048];   // Wg^T [n=1024][k=2048]

__constant__ int c_TI[10] = {0,1,1,2,2,2,3,3,3,3};
__constant__ int c_TJ[10] = {0,0,1,0,1,2,0,1,2,3};

// ================= helpers =================
__device__ __forceinline__ uint32_t smem_u32(const void* p) {
    uint32_t a;
    asm("{ .reg .u64 t; cvta.to.shared.u64 t, %1; cvt.u32.u64 %0, t; }" : "=r"(a) : "l"(p));
    return a;
}
__device__ __forceinline__ float silu_f(float v) { return v / (1.0f + expf(-v)); }

__device__ __forceinline__ void ldm_x4(uint32_t* r, uint32_t addr) {
    asm volatile("ldmatrix.sync.aligned.m8n8.x4.shared.b16 {%0,%1,%2,%3}, [%4];"
        : "=r"(r[0]), "=r"(r[1]), "=r"(r[2]), "=r"(r[3]) : "r"(addr));
}
__device__ __forceinline__ void mma16816(float* d, const uint32_t* a, uint32_t b0, uint32_t b1) {
    asm volatile("mma.sync.aligned.m16n8k16.row.col.f32.f16.f16.f32 "
        "{%0,%1,%2,%3},{%4,%5,%6,%7},{%8,%9},{%0,%1,%2,%3};"
        : "+f"(d[0]), "+f"(d[1]), "+f"(d[2]), "+f"(d[3])
        : "r"(a[0]), "r"(a[1]), "r"(a[2]), "r"(a[3]), "r"(b0), "r"(b1));
}

// cp.async ROWS x 32-half tile (64B/row), XOR-swizzled 16B chunks; g pre-offset to (row0,k)
template<int ROWS>
__device__ __forceinline__ void cp_rows(__half* s, const __half* __restrict__ g,
                                        int ld, int tid) {
#pragma unroll
    for (int i = 0; i < ROWS / 64; i++) {
        int cid = tid + 256 * i;
        int row = cid >> 2, c = cid & 3;
        const __half* gp = g + (size_t)row * ld + c * 8;
        int sc = c ^ ((row >> 1) & 3);
        uint32_t d = smem_u32(s + row * 32 + sc * 8);
        asm volatile("cp.async.cg.shared.global [%0], [%1], 16;" :: "r"(d), "l"(gp));
    }
}

// ============ 1-term fp16 mma.sync GEMM: C = A@B^T + bias ============
// MODE 0: A = Ah0 [M,1024]
// MODE 1: A = concat(Ah0, Ah1) along K (K=2048)
// MODE 2: gram: per-batch lower tiles; EPI 2: write ONLY Ch = fp16(-SC*(xx^T+1))
// EPI 1: also write fp16(C) to Ch
template<int MODE, int EPI>
__global__ __launch_bounds__(256, 2)
void gemm_mma(const __half* __restrict__ Ah0, const __half* __restrict__ Ah1,
              const __half* __restrict__ Bh, const float* __restrict__ bias,
              float* __restrict__ C, __half* __restrict__ Ch,
              int ldb, int ldc)
{
    extern __shared__ __align__(16) __half smem[];
    constexpr int SSTRIDE = 8192;   // halves per stage: A(4096) + B(4096)

    const int tid = threadIdx.x;
    const int warp = tid >> 5, lane = tid & 31;
    const int warpM = warp & 3, warpN = warp >> 2;   // 4 x 2 warps (32x64 each)
    const int K = (MODE == 1) ? 2048 : 1024;
    const int NS = K >> 5;

    size_t arow, brow; int crow0, ccol0, ldcc; float* cb;
    if (MODE == 2) {
        const int b = blockIdx.y;
        crow0 = c_TI[blockIdx.x] << 7; ccol0 = c_TJ[blockIdx.x] << 7;
        arow = (size_t)b * S_ + crow0; brow = (size_t)b * S_ + ccol0;
        cb = C; ldcc = S_;
        Ch = Ch + (size_t)b * S_ * S_;
    } else {
        arow = (size_t)blockIdx.y << 7; brow = (size_t)blockIdx.x << 7;
        crow0 = (int)arow; ccol0 = (int)brow; cb = C; ldcc = ldc;
    }

#define LOAD_STAGE(s_) do { \
        const int s__ = (s_); const int k0_ = s__ << 5; \
        __half* st_ = smem + (s__ % 3) * SSTRIDE; \
        if (MODE == 2) { \
            cp_rows<128>(st_,        Ah0 + arow * 1024 + k0_, 1024, tid); \
            cp_rows<128>(st_ + 4096, Ah0 + brow * 1024 + k0_, 1024, tid); \
        } else { \
            const __half* ah_ = Ah0; int ak_ = k0_; \
            if (MODE == 1 && k0_ >= 1024) { ah_ = Ah1; ak_ = k0_ - 1024; } \
            cp_rows<128>(st_,        ah_ + arow * 1024 + ak_, 1024, tid); \
            cp_rows<128>(st_ + 4096, Bh + brow * (size_t)ldb + k0_, ldb, tid); \
        } \
        asm volatile("cp.async.commit_group;" ::: "memory"); \
    } while (0)

    float acc[2][8][4];
#pragma unroll
    for (int mt = 0; mt < 2; mt++)
#pragma unroll
        for (int j = 0; j < 8; j++)
#pragma unroll
            for (int q = 0; q < 4; q++) acc[mt][j][q] = 0.0f;

    LOAD_STAGE(0);
    LOAD_STAGE(1);

    for (int s = 0; s < NS; s++) {
        if (s + 1 < NS) asm volatile("cp.async.wait_group 1;" ::: "memory");
        else            asm volatile("cp.async.wait_group 0;" ::: "memory");
        __syncthreads();
        const __half* st = smem + (s % 3) * SSTRIDE;
        const __half* Ahs = st;
        const __half* Bhs = st + 4096;
#pragma unroll
        for (int kk = 0; kk < 2; kk++) {
            const int q = lane >> 3, r = lane & 7;
            uint32_t af[2][4];
#pragma unroll
            for (int mt = 0; mt < 2; mt++) {
                const int row = warpM * 32 + mt * 16 + ((q & 1) ? 8 : 0) + r;
                const int c = kk * 2 + (q >> 1);
                ldm_x4(af[mt], smem_u32(Ahs + row * 32 + (c ^ ((row >> 1) & 3)) * 8));
            }
            uint32_t bf[4][4];
#pragma unroll
            for (int nt = 0; nt < 4; nt++) {
                const int row = warpN * 64 + nt * 16 + ((q >> 1) ? 8 : 0) + r;
                const int c = kk * 2 + (q & 1);
                ldm_x4(bf[nt], smem_u32(Bhs + row * 32 + (c ^ ((row >> 1) & 3)) * 8));
            }
#pragma unroll
            for (int mt = 0; mt < 2; mt++)
#pragma unroll
                for (int nt = 0; nt < 4; nt++) {
                    mma16816(acc[mt][nt * 2 + 0], af[mt], bf[nt][0], bf[nt][1]);
                    mma16816(acc[mt][nt * 2 + 1], af[mt], bf[nt][2], bf[nt][3]);
                }
        }
        if (s + 2 < NS) LOAD_STAGE(s + 2);
    }
#undef LOAD_STAGE

    // epilogue
    const int baseRow = crow0 + warpM * 32;
    const int baseCol = ccol0 + warpN * 64;
#pragma unroll
    for (int mt = 0; mt < 2; mt++) {
#pragma unroll
        for (int j = 0; j < 8; j++) {
            const int col = baseCol + j * 8 + (lane & 3) * 2;
            const int r0 = baseRow + mt * 16 + (lane >> 2);
            float bx, by;
            if (MODE == 2) { bx = 1.0f; by = 1.0f; }
            else { bx = bias[col]; by = bias[col + 1]; }
            float v0 = acc[mt][j][0] + bx, v1 = acc[mt][j][1] + by;
            float v2 = acc[mt][j][2] + bx, v3 = acc[mt][j][3] + by;
            if (EPI != 2) {
                *reinterpret_cast<float2*>(cb + (size_t)r0 * ldcc + col) = make_float2(v0, v1);
                *reinterpret_cast<float2*>(cb + (size_t)(r0 + 8) * ldcc + col) = make_float2(v2, v3);
            }
            if (EPI == 1) {
                *reinterpret_cast<__half2*>(Ch + (size_t)r0 * ldcc + col) =
                    __halves2half2(__float2half_rn(v0), __float2half_rn(v1));
                *reinterpret_cast<__half2*>(Ch + (size_t)(r0 + 8) * ldcc + col) =
                    __halves2half2(__float2half_rn(v2), __float2half_rn(v3));
            }
            if (EPI == 2) {   // Cs16 = fp16(-SC * (gram+1))
                *reinterpret_cast<__half2*>(Ch + (size_t)r0 * ldcc + col) =
                    __halves2half2(__float2half_rn(-SC * v0), __float2half_rn(-SC * v1));
                *reinterpret_cast<__half2*>(Ch + (size_t)(r0 + 8) * ldcc + col) =
                    __halves2half2(__float2half_rn(-SC * v2), __float2half_rn(-SC * v3));
            }
        }
    }
}

// ================= prep kernels =================
__global__ void conv_x_kernel(const float* __restrict__ x, __half* __restrict__ xh) {
    size_t i = ((size_t)blockIdx.x * 256 + threadIdx.x) * 4;
    float4 v = *reinterpret_cast<const float4*>(x + i);
    *reinterpret_cast<__half2*>(xh + i) =
        __halves2half2(__float2half_rn(v.x), __float2half_rn(v.y));
    *reinterpret_cast<__half2*>(xh + i + 2) =
        __halves2half2(__float2half_rn(v.z), __float2half_rn(v.w));
}

// oh[(n+roff)*ldo + k] = fp16(W[k][n] - Wsub?[k][n]);  W is [K, N] row-major
__global__ void ttrans_kernel(const float* __restrict__ W, const float* __restrict__ Wsub,
                              __half* __restrict__ oh, int N, int ldo, int roff)
{
    __shared__ float t[32][33];
    const int k0 = blockIdx.x * 32, n0 = blockIdx.y * 32;
    const int tx = threadIdx.x, ty = threadIdx.y;
#pragma unroll
    for (int i = 0; i < 32; i += 8) {
        float v = W[(size_t)(k0 + ty + i) * N + n0 + tx];
        if (Wsub) v -= Wsub[(size_t)(k0 + ty + i) * N + n0 + tx];
        t[ty + i][tx] = v;
    }
    __syncthreads();
#pragma unroll
    for (int i = 0; i < 32; i += 8)
        oh[(size_t)(n0 + ty + i + roff) * ldo + k0 + tx] = __float2half_rn(t[tx][ty + i]);
}

__global__ void bcat_kernel(const float* __restrict__ bt, const float* __restrict__ bi,
                            float* __restrict__ bc) {
    int j = blockIdx.x * 256 + threadIdx.x;
    if (j < 1024) bc[j] = bt[j];
    else if (j < 2048) bc[j] = bi[j - 1024] - bt[j - 1024];
}

// ================= triangular inverse per (batch, chunk), from Cs16 =================
__global__ __launch_bounds__(64) void tri_inv_kernel()
{
    __shared__ float L[64][65];
    __shared__ float Msm[64][65];
    const int bc = blockIdx.x, b = bc >> 3, ch = bc & 7;
    const int j = threadIdx.x;
    const __half* Cb = g_Cs16 + (size_t)b * S_ * S_ + (size_t)(ch * 64) * S_ + ch * 64;
    for (int r = 0; r < 64; r++) L[r][j] = __half2float(Cb[(size_t)r * S_ + j]);
    for (int t = 0; t < 64; t++) Msm[t][j] = (t == j) ? 1.0f : 0.0f;
    __syncthreads();
    for (int t = 1; t < 64; t++) {
        if (t > j) {
            float a = 0.0f;
            for (int s = j; s < t; s++) a += L[t][s] * Msm[s][j];
            Msm[t][j] = a;
        }
    }
    float* Mo = g_Minv + (size_t)bc * 64 * 64;
    for (int r = 0; r < 64; r++) Mo[r * 64 + j] = Msm[r][j];
}

// ================= fused chunked solve + silu, pipelined pc loop =================
// grid (8 colblks, 64 batches); chunk loop internal; double-buffered (Cs,EhT) stages.
__global__ __launch_bounds__(256) void solve_all_kernel()
{
    extern __shared__ __align__(16) char sm[];
    // two stage buffers, each: As0(2048) As1(2048) Bs0(4096) Bs1(4096) = 12288 halves
    __half* buf0 = (__half*)sm;
    __half* buf1 = buf0 + 12288;
    float*  Rf  = (float*)(buf1 + 12288);   // [64][132]
    float*  Ms  = Rf + 64 * 132;            // [64][65]

    const int tid = threadIdx.x;
    const int warp = tid >> 5, lane = tid & 31;
    const int warpM = warp & 3, warpN = warp >> 2;
    const int b = blockIdx.y;
    const int col0 = blockIdx.x << 7;
    const float* TEb = g_TE + (size_t)b * S_ * 2048;          // T at +0, A at +1024
    const __half* CsB = g_Cs16 + (size_t)b * S_ * S_;
    __half* EhT = g_EhT + (size_t)b * 1024 * 512;
    __half* ShB = g_Sh + (size_t)b * S_ * 1024;

#define ISSUE_PC(pc_, bp_) do { \
        const __half* Cs_ = CsB + (size_t)(ch * 64) * S_ + (pc_) * 64; \
        cp_rows<64>((bp_),          Cs_,      S_, tid); \
        cp_rows<64>((bp_) + 2048,   Cs_ + 32, S_, tid); \
        const __half* Eg_ = EhT + (size_t)col0 * 512 + (pc_) * 64; \
        cp_rows<128>((bp_) + 4096,  Eg_,      512, tid); \
        cp_rows<128>((bp_) + 8192,  Eg_ + 32, 512, tid); \
        asm volatile("cp.async.commit_group;" ::: "memory"); \
    } while (0)

    for (int ch = 0; ch < 8; ch++) {
        float acc[8][4];
#pragma unroll
        for (int nt = 0; nt < 8; nt++)
#pragma unroll
            for (int q = 0; q < 4; q++) acc[nt][q] = 0.0f;

        // prefetch pc0/pc1
        if (ch > 0) ISSUE_PC(0, buf0);
        if (ch > 1) ISSUE_PC(1, buf1);

        // Minv fill (plain loads; latency overlaps the cp.async groups above)
        const float* Mo = g_Minv + (size_t)(b * 8 + ch) * 4096;
        for (int idx = tid; idx < 4096; idx += 256)
            Ms[(idx >> 6) * 65 + (idx & 63)] = Mo[idx];

        for (int pc = 0; pc < ch; pc++) {
            if (pc + 1 < ch) asm volatile("cp.async.wait_group 1;" ::: "memory");
            else             asm volatile("cp.async.wait_group 0;" ::: "memory");
            __syncthreads();
            const __half* bp = (pc & 1) ? buf1 : buf0;
            const __half* As0 = bp;
            const __half* As1 = bp + 2048;
            const __half* Bs0 = bp + 4096;
            const __half* Bs1 = bp + 8192;
#pragma unroll
            for (int kk = 0; kk < 4; kk++) {
                const __half* As = (kk < 2) ? As0 : As1;
                const __half* Bs = (kk < 2) ? Bs0 : Bs1;
                const int kl = kk & 1;
                const int q = lane >> 3, r = lane & 7;
                uint32_t af[4];
                {
                    const int row = warpM * 16 + ((q & 1) ? 8 : 0) + r;
                    const int c = kl * 2 + (q >> 1);
                    ldm_x4(af, smem_u32(As + row * 32 + (c ^ ((row >> 1) & 3)) * 8));
                }
                uint32_t bf[4][4];
#pragma unroll
                for (int ntc = 0; ntc < 4; ntc++) {
                    const int row = warpN * 64 + ntc * 16 + ((q >> 1) ? 8 : 0) + r;
                    const int c = kl * 2 + (q & 1);
                    ldm_x4(bf[ntc], smem_u32(Bs + row * 32 + (c ^ ((row >> 1) & 3)) * 8));
                }
#pragma unroll
                for (int ntc = 0; ntc < 4; ntc++) {
                    mma16816(acc[ntc * 2 + 0], af, bf[ntc][0], bf[ntc][1]);
                    mma16816(acc[ntc * 2 + 1], af, bf[ntc][2], bf[ntc][3]);
                }
            }
            __syncthreads();   // buffer free for refill
            if (pc + 2 < ch) ISSUE_PC(pc + 2, (pc & 1) ? buf1 : buf0);
        }

        // R = A + acc -> Rf
        {
            const int r0 = warpM * 16 + (lane >> 2);
            const float* Arow = TEb + (size_t)(ch * 64) * 2048 + 1024 + col0;
#pragma unroll
            for (int nt = 0; nt < 8; nt++) {
                const int col = warpN * 64 + nt * 8 + (lane & 3) * 2;
                float2 a0 = *reinterpret_cast<const float2*>(Arow + (size_t)r0 * 2048 + col);
                float2 a1 = *reinterpret_cast<const float2*>(Arow + (size_t)(r0 + 8) * 2048 + col);
                Rf[r0 * 132 + col]           = a0.x + acc[nt][0];
                Rf[r0 * 132 + col + 1]       = a0.y + acc[nt][1];
                Rf[(r0 + 8) * 132 + col]     = a1.x + acc[nt][2];
                Rf[(r0 + 8) * 132 + col + 1] = a1.y + acc[nt][3];
            }
        }
        __syncthreads();

        // E = Minv @ R (SIMT, K=64)
        const int ty = tid >> 4, tx = tid & 15;
        float e[4][8];
#pragma unroll
        for (int rr = 0; rr < 4; rr++)
#pragma unroll
            for (int cc = 0; cc < 8; cc++) e[rr][cc] = 0.0f;
        for (int qq = 0; qq < 64; qq++) {
            float mv[4];
#pragma unroll
            for (int rr = 0; rr < 4; rr++) mv[rr] = Ms[(ty * 4 + rr) * 65 + qq];
            float4 rv0 = *reinterpret_cast<const float4*>(&Rf[qq * 132 + tx * 8]);
            float4 rv1 = *reinterpret_cast<const float4*>(&Rf[qq * 132 + tx * 8 + 4]);
#pragma unroll
            for (int rr = 0; rr < 4; rr++) {
                e[rr][0] += mv[rr] * rv0.x; e[rr][1] += mv[rr] * rv0.y;
                e[rr][2] += mv[rr] * rv0.z; e[rr][3] += mv[rr] * rv0.w;
                e[rr][4] += mv[rr] * rv1.x; e[rr][5] += mv[rr] * rv1.y;
                e[rr][6] += mv[rr] * rv1.z; e[rr][7] += mv[rr] * rv1.w;
            }
        }

        // write EhT fp16 (consumed by later chunks)
#pragma unroll
        for (int cc = 0; cc < 8; cc++) {
            const int gcol = col0 + tx * 8 + cc;
            __half2 p0 = __halves2half2(__float2half_rn(e[0][cc]), __float2half_rn(e[1][cc]));
            __half2 p1 = __halves2half2(__float2half_rn(e[2][cc]), __float2half_rn(e[3][cc]));
            *reinterpret_cast<__half2*>(EhT + (size_t)gcol * 512 + ch * 64 + ty * 4)     = p0;
            *reinterpret_cast<__half2*>(EhT + (size_t)gcol * 512 + ch * 64 + ty * 4 + 2) = p1;
        }
        // fused: S = silu(T + E) -> fp16 Sh
#pragma unroll
        for (int rr = 0; rr < 4; rr++) {
            const int row = ch * 64 + ty * 4 + rr;
            const float* Trow = TEb + (size_t)row * 2048 + col0 + tx * 8;
            float4 t0 = *reinterpret_cast<const float4*>(Trow);
            float4 t1 = *reinterpret_cast<const float4*>(Trow + 4);
            __half2 s0 = __halves2half2(__float2half_rn(silu_f(t0.x + e[rr][0])),
                                        __float2half_rn(silu_f(t0.y + e[rr][1])));
            __half2 s1 = __halves2half2(__float2half_rn(silu_f(t0.z + e[rr][2])),
                                        __float2half_rn(silu_f(t0.w + e[rr][3])));
            __half2 s2 = __halves2half2(__float2half_rn(silu_f(t1.x + e[rr][4])),
                                        __float2half_rn(silu_f(t1.y + e[rr][5])));
            __half2 s3 = __halves2half2(__float2half_rn(silu_f(t1.z + e[rr][6])),
                                        __float2half_rn(silu_f(t1.w + e[rr][7])));
            __half* Srow = ShB + (size_t)row * 1024 + col0 + tx * 8;
            *reinterpret_cast<__half2*>(Srow)     = s0;
            *reinterpret_cast<__half2*>(Srow + 2) = s1;
            *reinterpret_cast<__half2*>(Srow + 4) = s2;
            *reinterpret_cast<__half2*>(Srow + 6) = s3;
        }
        __syncthreads();   // EhT visible + smem reusable for next chunk
    }
#undef ISSUE_PC
}

// ================= fused sigmoid-gate + LayerNorm =================
__global__ __launch_bounds__(256) void gate_ln_kernel(
    const float* __restrict__ Z, const float* __restrict__ T, const float* __restrict__ X,
    const float* __restrict__ gamma, const float* __restrict__ beta, float* __restrict__ out)
{
    __shared__ float red[16];
    __shared__ float mu_s, rinv_s;
    const int n = blockIdx.x, tid = threadIdx.x;
    const size_t base = (size_t)n * H_ + tid * 4;
    float4 z = *(const float4*)(Z + base);
    float4 t = *(const float4*)(T + base);
    float4 x = *(const float4*)(X + base);
    float h[4];
    {
        float g;
        g = 1.0f / (1.0f + expf(-z.x)); h[0] = g * t.x + (1.0f - g) * x.x;
        g = 1.0f / (1.0f + expf(-z.y)); h[1] = g * t.y + (1.0f - g) * x.y;
        g = 1.0f / (1.0f + expf(-z.z)); h[2] = g * t.z + (1.0f - g) * x.z;
        g = 1.0f / (1.0f + expf(-z.w)); h[3] = g * t.w + (1.0f - g) * x.w;
    }
    float s = h[0] + h[1] + h[2] + h[3];
    float q = h[0]*h[0] + h[1]*h[1] + h[2]*h[2] + h[3]*h[3];
#pragma unroll
    for (int o = 16; o > 0; o >>= 1) {
        s += __shfl_xor_sync(0xffffffffu, s, o);
        q += __shfl_xor_sync(0xffffffffu, q, o);
    }
    const int lane = tid & 31, wid = tid >> 5;
    if (lane == 0) { red[wid] = s; red[8 + wid] = q; }
    __syncthreads();
    if (tid == 0) {
        float Sa = 0.0f, Q = 0.0f;
#pragma unroll
        for (int w = 0; w < 8; w++) { Sa += red[w]; Q += red[8 + w]; }
        float mu = Sa * (1.0f / H_);
        mu_s = mu; rinv_s = rsqrtf(Q * (1.0f / H_) - mu * mu + EPS_);
    }
    __syncthreads();
    const float mu = mu_s, rinv = rinv_s;
    float4 gm = *(const float4*)(gamma + tid * 4);
    float4 bt = *(const float4*)(beta + tid * 4);
    float4 o;
    o.x = (h[0] - mu) * rinv * gm.x + bt.x;
    o.y = (h[1] - mu) * rinv * gm.y + bt.y;
    o.z = (h[2] - mu) * rinv * gm.z + bt.z;
    o.w = (h[3] - mu) * rinv * gm.w + bt.w;
    *(float4*)(out + base) = o;
}

// ================= launch =================
extern "C" void kernel_launch(void* const* d_in, const int* in_sizes, int n_in,
                              void* d_out, int out_size)
{
    const float* x      = (const float*)d_in[0];
    const float* W_init = (const float*)d_in[1];
    const float* b_init = (const float*)d_in[2];
    const float* Wt     = (const float*)d_in[3];
    const float* bt     = (const float*)d_in[4];
    const float* Wo     = (const float*)d_in[5];
    const float* bo     = (const float*)d_in[6];
    const float* Wg     = (const float*)d_in[7];
    const float* bg     = (const float*)d_in[8];
    const float* gamma  = (const float*)d_in[9];
    const float* beta   = (const float*)d_in[10];
    float* out = (float*)d_out;

    float *pTE, *pTT, *pZ, *pbc;
    __half *pxh, *pSh, *pTTh, *pBh, *pWoh, *pWgh, *pCs;
    cudaGetSymbolAddress((void**)&pTE,  g_TE);
    cudaGetSymbolAddress((void**)&pTT,  g_ttt);
    cudaGetSymbolAddress((void**)&pZ,   g_Z);
    cudaGetSymbolAddress((void**)&pCs,  g_Cs16);
    cudaGetSymbolAddress((void**)&pbc,  g_bcat);
    cudaGetSymbolAddress((void**)&pxh,  g_xh);
    cudaGetSymbolAddress((void**)&pSh,  g_Sh);
    cudaGetSymbolAddress((void**)&pTTh, g_TTh);
    cudaGetSymbolAddress((void**)&pBh,  g_Bh);
    cudaGetSymbolAddress((void**)&pWoh, g_Woh);
    cudaGetSymbolAddress((void**)&pWgh, g_Wgh);

    const int SMB = 3 * 8192 * 2;                       // 49152 B
    const int SMS = 2 * 12288 * 2 + 64 * 132 * 4 + 64 * 65 * 4;   // 99584 B
    cudaFuncSetAttribute(gemm_mma<0,0>, cudaFuncAttributeMaxDynamicSharedMemorySize, SMB);
    cudaFuncSetAttribute(gemm_mma<0,1>, cudaFuncAttributeMaxDynamicSharedMemorySize, SMB);
    cudaFuncSetAttribute(gemm_mma<1,0>, cudaFuncAttributeMaxDynamicSharedMemorySize, SMB);
    cudaFuncSetAttribute(gemm_mma<2,2>, cudaFuncAttributeMaxDynamicSharedMemorySize, SMB);
    cudaFuncSetAttribute(solve_all_kernel, cudaFuncAttributeMaxDynamicSharedMemorySize, SMS);

    dim3 tb(32, 8);
    conv_x_kernel<<<N_ * H_ / 1024, 256>>>(x, pxh);
    ttrans_kernel<<<dim3(32, 32), tb>>>(Wt, nullptr, pBh, 1024, 1024, 0);
    ttrans_kernel<<<dim3(32, 32), tb>>>(W_init, Wt, pBh, 1024, 1024, 1024);
    ttrans_kernel<<<dim3(32, 32), tb>>>(Wo, nullptr, pWoh, 1024, 1024, 0);
    ttrans_kernel<<<dim3(64, 32), tb>>>(Wg, nullptr, pWgh, 1024, 2048, 0);
    bcat_kernel<<<8, 256>>>(bt, b_init, pbc);

    // [T | A] = x @ [Wt | Winit-Wt] + [bt | binit-bt]  (N=2048)
    gemm_mma<0,0><<<dim3(16, 256), 256, SMB>>>(pxh, nullptr, pBh, pbc,
                                               pTE, nullptr, 1024, 2048);
    // Gram lower tiles -> Cs16 = fp16(-SC*(xx^T+1))
    gemm_mma<2,2><<<dim3(10, 64), 256, SMB>>>(pxh, nullptr, nullptr, nullptr,
                                              nullptr, pCs, 1024, 0);
    tri_inv_kernel<<<512, 64>>>();
    // single fused pipelined solve + silu -> Sh
    solve_all_kernel<<<dim3(8, 64), 256, SMS>>>();
    // ttt = S @ Wo + bo (EPI writes fp16 copy)
    gemm_mma<0,1><<<dim3(8, 256), 256, SMB>>>(pSh, nullptr, pWoh, bo,
                                              pTT, pTTh, 1024, 1024);
    // Z = [x, ttt] @ Wg + bg
    gemm_mma<1,0><<<dim3(8, 256), 256, SMB>>>(pxh, pTTh, pWgh, bg,
                                              pZ, nullptr, 2048, 1024);
    // out = LN(sigmoid(Z)*ttt + (1-sigmoid(Z))*x)
    gate_ln_kernel<<<N_, 256>>>(pZ, pTT, x, gamma, beta, out);
}